// round 3
// baseline (speedup 1.0000x reference)
#include <cuda_runtime.h>
#include <math.h>

#define BATCH 16
#define CCH   256
#define NTOK  1024
#define NN    (1024*1024)
#define NHEAD 8
#define HID   1024
#define MTOT  (BATCH*NTOK)   // 16384

typedef unsigned long long ull;

// ---------------- f32x2 packed-FP32 helpers ----------------
__device__ __forceinline__ void fma2(ull &d, ull a, ull b) {
    asm("fma.rn.f32x2 %0, %1, %2, %0;" : "+l"(d) : "l"(a), "l"(b));
}
__device__ __forceinline__ void add2(ull &d, ull a) {
    asm("add.rn.f32x2 %0, %0, %1;" : "+l"(d) : "l"(a));
}
__device__ __forceinline__ ull pk2(float x, float y) {
    ull r; asm("mov.b64 %0, {%1, %2};" : "=l"(r) : "f"(x), "f"(y)); return r;
}
__device__ __forceinline__ float2 up2(ull v) {
    float2 r; asm("mov.b64 {%0, %1}, %2;" : "=f"(r.x), "=f"(r.y) : "l"(v)); return r;
}

// ---------------- scratch ----------------
__device__ float g_x1  [MTOT*CCH];
__device__ float g_qkv [MTOT*3*CCH];
__device__ float g_bias[NHEAD*NN];
__device__ float g_attn[MTOT*CCH];
__device__ float g_x3  [MTOT*CCH];
__device__ float g_x4  [MTOT*CCH];
__device__ float g_ffn [MTOT*HID];

// ---------------- bias expand ----------------
__global__ void __launch_bounds__(256) expand_bias_k(
    const float* __restrict__ table, const int* __restrict__ relidx,
    float* __restrict__ biasF)
{
    int t = blockIdx.x * 256 + threadIdx.x;
    int idx = relidx[t];
    #pragma unroll
    for (int h = 0; h < NHEAD; h++)
        biasF[(size_t)h * NN + t] = table[idx * NHEAD + h];
}

// ---------------- block reduction ----------------
__device__ __forceinline__ float block_sum_256(float v, float* sh)
{
    __syncthreads();
    int lane = threadIdx.x & 31, wid = threadIdx.x >> 5;
    #pragma unroll
    for (int o = 16; o; o >>= 1) v += __shfl_xor_sync(0xffffffffu, v, o);
    if (!lane) sh[wid] = v;
    __syncthreads();
    if (threadIdx.x < 8) {
        float t = sh[threadIdx.x];
        #pragma unroll
        for (int o = 4; o; o >>= 1) t += __shfl_xor_sync(0xffu, t, o);
        if (!threadIdx.x) sh[0] = t;
    }
    __syncthreads();
    return sh[0];
}

// ---------------- LayerNorm ----------------
template<int TRANSPOSED>
__global__ void __launch_bounds__(256) ln_k(
    const float* __restrict__ in, const float* __restrict__ w,
    const float* __restrict__ bsh, float* __restrict__ out)
{
    __shared__ float sh[8];
    int token = blockIdx.x;
    int c = threadIdx.x;
    float v;
    if (TRANSPOSED) {
        int bb = token >> 10, p = token & 1023;
        v = in[((size_t)bb * CCH + c) * NTOK + p];
    } else {
        v = in[(size_t)token * CCH + c];
    }
    float mu  = block_sum_256(v, sh) * (1.0f / 256.0f);
    float d   = v - mu;
    float var = block_sum_256(d * d, sh) * (1.0f / 256.0f);
    out[(size_t)token * CCH + c] = d * rsqrtf(var + 1e-5f) * w[c] + bsh[c];
}

// ---------------- 128x128x16 GEMM, f32x2, register prefetch ----------------
template<int EPI>
__global__ void __launch_bounds__(256, 2) gemm2_k(
    const float* __restrict__ A, const float* __restrict__ Bm,
    const float* __restrict__ bias, float* __restrict__ C,
    int M, int N, int K,
    const float* __restrict__ aux, float* __restrict__ aux2)
{
    __shared__ ull   Asd[16][128];
    __shared__ float Bs [16][128];

    const int tid = threadIdx.x;
    const int tx = tid & 15;
    const int ty = tid >> 4;
    const int row0 = blockIdx.y * 128;
    const int col0 = blockIdx.x * 128;

    ull acc[8][4] = {};

    const int am = tid >> 1, ak = (tid & 1) * 8;
    const int bk = tid >> 4, bn = (tid & 15) * 8;
    const float* Aptr = A + (size_t)(row0 + am) * K + ak;
    const float* Bptr = Bm + (size_t)bk * N + col0 + bn;

    float4 av0 = *(const float4*)(Aptr);
    float4 av1 = *(const float4*)(Aptr + 4);
    float4 bv0 = *(const float4*)(Bptr);
    float4 bv1 = *(const float4*)(Bptr + 4);

    for (int k0 = 0; k0 < K; k0 += 16) {
        __syncthreads();
        Asd[ak + 0][am] = pk2(av0.x, av0.x);
        Asd[ak + 1][am] = pk2(av0.y, av0.y);
        Asd[ak + 2][am] = pk2(av0.z, av0.z);
        Asd[ak + 3][am] = pk2(av0.w, av0.w);
        Asd[ak + 4][am] = pk2(av1.x, av1.x);
        Asd[ak + 5][am] = pk2(av1.y, av1.y);
        Asd[ak + 6][am] = pk2(av1.z, av1.z);
        Asd[ak + 7][am] = pk2(av1.w, av1.w);
        *(float4*)&Bs[bk][bn]     = bv0;
        *(float4*)&Bs[bk][bn + 4] = bv1;
        __syncthreads();
        if (k0 + 16 < K) {
            av0 = *(const float4*)(Aptr + k0 + 16);
            av1 = *(const float4*)(Aptr + k0 + 20);
            bv0 = *(const float4*)(Bptr + (size_t)(k0 + 16) * N);
            bv1 = *(const float4*)(Bptr + (size_t)(k0 + 16) * N + 4);
        }
        #pragma unroll
        for (int kk = 0; kk < 16; kk++) {
            ulonglong2 a01 = *(const ulonglong2*)&Asd[kk][ty * 8 + 0];
            ulonglong2 a23 = *(const ulonglong2*)&Asd[kk][ty * 8 + 2];
            ulonglong2 a45 = *(const ulonglong2*)&Asd[kk][ty * 8 + 4];
            ulonglong2 a67 = *(const ulonglong2*)&Asd[kk][ty * 8 + 6];
            ulonglong2 b01 = *(const ulonglong2*)&Bs[kk][tx * 8];
            ulonglong2 b23 = *(const ulonglong2*)&Bs[kk][tx * 8 + 4];
            ull aa[8] = {a01.x, a01.y, a23.x, a23.y, a45.x, a45.y, a67.x, a67.y};
            ull bb[4] = {b01.x, b01.y, b23.x, b23.y};
            #pragma unroll
            for (int i = 0; i < 8; i++)
                #pragma unroll
                for (int j = 0; j < 4; j++)
                    fma2(acc[i][j], aa[i], bb[j]);
        }
    }

    #pragma unroll
    for (int i = 0; i < 8; i++) {
        int m = row0 + ty * 8 + i;
        #pragma unroll
        for (int j = 0; j < 4; j++) {
            float2 v2 = up2(acc[i][j]);
            int n = col0 + tx * 8 + j * 2;
            #pragma unroll
            for (int e = 0; e < 2; e++) {
                float v = e ? v2.y : v2.x;
                int nn = n + e;
                if (EPI == 0) {
                    C[(size_t)m * N + nn] = v;
                } else if (EPI == 1) {
                    int bb2 = m >> 10, p = m & 1023;
                    v += bias[nn] + aux[((size_t)bb2 * CCH + nn) * NTOK + p];
                    C[(size_t)m * N + nn] = v;
                } else if (EPI == 2) {
                    v += bias[nn];
                    v = 0.5f * v * (1.0f + erff(v * 0.7071067811865475f));
                    C[(size_t)m * N + nn] = v;
                } else {
                    int bb2 = m >> 10, p = m & 1023;
                    v += bias[nn] + aux[(size_t)m * CCH + nn];
                    aux2[((size_t)bb2 * CCH + nn) * NTOK + p] = v;
                }
            }
        }
    }
}

// ---------------- fused flash attention, register-tiled, f32x2 ----------------
// 64 q-tile; QK: thread = 4q x 4k mini-GEMM; PV: thread = 2q(pair) x 4d,
// P pairs loaded as native ull, V pre-duplicated {v,v} in swizzled smem.
__global__ void __launch_bounds__(256, 3) attn_k(
    const float* __restrict__ qkv, const float* __restrict__ biasF,
    float* __restrict__ out)
{
    __shared__ float Qt [32][64];   // [d][q]
    __shared__ float Kt [32][64];   // [d][key]
    __shared__ ull   Vsd[64][32];   // [key][d] duplicated pairs, xor-swizzled
    __shared__ float Pt [64][64];   // [key][q]

    const int q0 = blockIdx.x * 64;
    const int h  = blockIdx.y;
    const int b  = blockIdx.z;
    const int tid = threadIdx.x;
    const int tx = tid & 15, ty = tid >> 4;        // QK mapping
    const int lr = tid >> 2, ldq = (tid & 3) * 8;  // load mapping
    const int qg = tid >> 3, dg = tid & 7;         // PV mapping

    // load Q tile transposed
    {
        const float* qp = qkv + (size_t)(b * NTOK + q0 + lr) * 768 + h * 32 + ldq;
        float4 a = *(const float4*)qp;
        float4 c = *(const float4*)(qp + 4);
        Qt[ldq + 0][lr] = a.x; Qt[ldq + 1][lr] = a.y;
        Qt[ldq + 2][lr] = a.z; Qt[ldq + 3][lr] = a.w;
        Qt[ldq + 4][lr] = c.x; Qt[ldq + 5][lr] = c.y;
        Qt[ldq + 6][lr] = c.z; Qt[ldq + 7][lr] = c.w;
    }

    ull o0 = 0, o1 = 0, o2 = 0, o3 = 0, lsum = 0;
    const float scale = 0.17677669529663687f;   // 32^-0.5
    const float* bb0 = biasF + ((size_t)h << 20) + (size_t)(q0 + ty * 4) * NTOK + tx * 4;
    const int sw = (lr & 7) << 2;

    for (int kt = 0; kt < 16; kt++) {
        __syncthreads();
        // load K (transposed) and V (duplicated, swizzled)
        const float* kp = qkv + (size_t)(b * NTOK + kt * 64 + lr) * 768
                          + 256 + h * 32 + ldq;
        float4 ka = *(const float4*)kp;
        float4 kc = *(const float4*)(kp + 4);
        float4 va = *(const float4*)(kp + 256);
        float4 vc = *(const float4*)(kp + 260);
        Kt[ldq + 0][lr] = ka.x; Kt[ldq + 1][lr] = ka.y;
        Kt[ldq + 2][lr] = ka.z; Kt[ldq + 3][lr] = ka.w;
        Kt[ldq + 4][lr] = kc.x; Kt[ldq + 5][lr] = kc.y;
        Kt[ldq + 6][lr] = kc.z; Kt[ldq + 7][lr] = kc.w;
        Vsd[lr][(ldq + 0) ^ sw] = pk2(va.x, va.x);
        Vsd[lr][(ldq + 1) ^ sw] = pk2(va.y, va.y);
        Vsd[lr][(ldq + 2) ^ sw] = pk2(va.z, va.z);
        Vsd[lr][(ldq + 3) ^ sw] = pk2(va.w, va.w);
        Vsd[lr][(ldq + 4) ^ sw] = pk2(vc.x, vc.x);
        Vsd[lr][(ldq + 5) ^ sw] = pk2(vc.y, vc.y);
        Vsd[lr][(ldq + 6) ^ sw] = pk2(vc.z, vc.z);
        Vsd[lr][(ldq + 7) ^ sw] = pk2(vc.w, vc.w);
        // prefetch bias rows for this tile (4 queries x 4 keys)
        float4 bi0 = *(const float4*)(bb0 + kt * 64);
        float4 bi1 = *(const float4*)(bb0 + NTOK + kt * 64);
        float4 bi2 = *(const float4*)(bb0 + 2 * NTOK + kt * 64);
        float4 bi3 = *(const float4*)(bb0 + 3 * NTOK + kt * 64);
        __syncthreads();

        // ---- QK: 4q x 4k ----
        ull acc[4][2] = {};
        #pragma unroll
        for (int d = 0; d < 32; d++) {
            float4 qv = *(const float4*)&Qt[d][ty * 4];
            ulonglong2 kk2 = *(const ulonglong2*)&Kt[d][tx * 4];
            ull qd0 = pk2(qv.x, qv.x), qd1 = pk2(qv.y, qv.y);
            ull qd2 = pk2(qv.z, qv.z), qd3 = pk2(qv.w, qv.w);
            fma2(acc[0][0], qd0, kk2.x); fma2(acc[0][1], qd0, kk2.y);
            fma2(acc[1][0], qd1, kk2.x); fma2(acc[1][1], qd1, kk2.y);
            fma2(acc[2][0], qd2, kk2.x); fma2(acc[2][1], qd2, kk2.y);
            fma2(acc[3][0], qd3, kk2.x); fma2(acc[3][1], qd3, kk2.y);
        }
        float p[4][4];
        {
            float2 s0 = up2(acc[0][0]), s1 = up2(acc[0][1]);
            p[0][0] = __expf(fmaf(s0.x, scale, bi0.x));
            p[0][1] = __expf(fmaf(s0.y, scale, bi0.y));
            p[0][2] = __expf(fmaf(s1.x, scale, bi0.z));
            p[0][3] = __expf(fmaf(s1.y, scale, bi0.w));
            s0 = up2(acc[1][0]); s1 = up2(acc[1][1]);
            p[1][0] = __expf(fmaf(s0.x, scale, bi1.x));
            p[1][1] = __expf(fmaf(s0.y, scale, bi1.y));
            p[1][2] = __expf(fmaf(s1.x, scale, bi1.z));
            p[1][3] = __expf(fmaf(s1.y, scale, bi1.w));
            s0 = up2(acc[2][0]); s1 = up2(acc[2][1]);
            p[2][0] = __expf(fmaf(s0.x, scale, bi2.x));
            p[2][1] = __expf(fmaf(s0.y, scale, bi2.y));
            p[2][2] = __expf(fmaf(s1.x, scale, bi2.z));
            p[2][3] = __expf(fmaf(s1.y, scale, bi2.w));
            s0 = up2(acc[3][0]); s1 = up2(acc[3][1]);
            p[3][0] = __expf(fmaf(s0.x, scale, bi3.x));
            p[3][1] = __expf(fmaf(s0.y, scale, bi3.y));
            p[3][2] = __expf(fmaf(s1.x, scale, bi3.z));
            p[3][3] = __expf(fmaf(s1.y, scale, bi3.w));
        }
        #pragma unroll
        for (int kk = 0; kk < 4; kk++)
            *(float4*)&Pt[tx * 4 + kk][ty * 4] =
                make_float4(p[0][kk], p[1][kk], p[2][kk], p[3][kk]);
        __syncthreads();

        // ---- PV: q-pair x 4d ----
        #pragma unroll 8
        for (int j = 0; j < 64; j++) {
            ull p01 = *(const ull*)&Pt[j][qg * 2];
            add2(lsum, p01);
            int swj = (j & 7) << 2;
            ulonglong2 vda = *(const ulonglong2*)&Vsd[j][(dg * 4) ^ swj];
            ulonglong2 vdb = *(const ulonglong2*)&Vsd[j][((dg * 4) ^ swj) + 2];
            fma2(o0, p01, vda.x);
            fma2(o1, p01, vda.y);
            fma2(o2, p01, vdb.x);
            fma2(o3, p01, vdb.y);
        }
    }

    float2 lf = up2(lsum);
    float i0 = 1.0f / lf.x, i1 = 1.0f / lf.y;
    float2 a0 = up2(o0), a1 = up2(o1), a2 = up2(o2), a3 = up2(o3);
    float* op = out + (size_t)(b * NTOK + q0 + qg * 2) * CCH + h * 32 + dg * 4;
    *(float4*)op         = make_float4(a0.x * i0, a1.x * i0, a2.x * i0, a3.x * i0);
    *(float4*)(op + CCH) = make_float4(a0.y * i1, a1.y * i1, a2.y * i1, a3.y * i1);
}

// ---------------- launch ----------------
extern "C" void kernel_launch(void* const* d_in, const int* in_sizes, int n_in,
                              void* d_out, int out_size)
{
    const float* x       = (const float*)d_in[0];
    const float* qkv_w   = (const float*)d_in[1];
    const float* proj_w  = (const float*)d_in[2];
    const float* proj_b  = (const float*)d_in[3];
    const float* ffn_w1  = (const float*)d_in[4];
    const float* ffn_b1  = (const float*)d_in[5];
    const float* ffn_w2  = (const float*)d_in[6];
    const float* ffn_b2  = (const float*)d_in[7];
    const float* n1w     = (const float*)d_in[8];
    const float* n1b     = (const float*)d_in[9];
    const float* n2w     = (const float*)d_in[10];
    const float* n2b     = (const float*)d_in[11];
    const float* table   = (const float*)d_in[12];
    const int*   relidx  = (const int*)d_in[13];
    float* out = (float*)d_out;

    void *px1, *pqkv, *pbias, *pattn, *px3, *px4, *pffn;
    cudaGetSymbolAddress(&px1,  g_x1);
    cudaGetSymbolAddress(&pqkv, g_qkv);
    cudaGetSymbolAddress(&pbias,g_bias);
    cudaGetSymbolAddress(&pattn,g_attn);
    cudaGetSymbolAddress(&px3,  g_x3);
    cudaGetSymbolAddress(&px4,  g_x4);
    cudaGetSymbolAddress(&pffn, g_ffn);

    expand_bias_k<<<NN / 256, 256>>>(table, relidx, (float*)pbias);
    ln_k<1><<<MTOT, 256>>>(x, n1w, n1b, (float*)px1);
    gemm2_k<0><<<dim3(768 / 128, MTOT / 128), 256>>>(
        (const float*)px1, qkv_w, nullptr, (float*)pqkv,
        MTOT, 768, 256, nullptr, nullptr);
    attn_k<<<dim3(16, NHEAD, BATCH), 256>>>(
        (const float*)pqkv, (const float*)pbias, (float*)pattn);
    gemm2_k<1><<<dim3(256 / 128, MTOT / 128), 256>>>(
        (const float*)pattn, proj_w, proj_b, (float*)px3,
        MTOT, 256, 256, x, nullptr);
    ln_k<0><<<MTOT, 256>>>((const float*)px3, n2w, n2b, (float*)px4);
    gemm2_k<2><<<dim3(HID / 128, MTOT / 128), 256>>>(
        (const float*)px4, ffn_w1, ffn_b1, (float*)pffn,
        MTOT, HID, 256, nullptr, nullptr);
    gemm2_k<3><<<dim3(256 / 128, MTOT / 128), 256>>>(
        (const float*)pffn, ffn_w2, ffn_b2, nullptr,
        MTOT, 256, 1024, (const float*)px3, out);
}

// round 4
// speedup vs baseline: 3.6179x; 3.6179x over previous
#include <cuda_runtime.h>
#include <math.h>
#include <stdint.h>

#define BATCH 16
#define CCH   256
#define NTOK  1024
#define NN    (1024*1024)
#define NHEAD 8
#define HID   1024
#define MTOT  (BATCH*NTOK)   // 16384

// ---------------- tf32 helpers ----------------
__device__ __forceinline__ uint32_t tf32c(float f) {
    uint32_t u; asm("cvt.rna.tf32.f32 %0, %1;" : "=r"(u) : "f"(f)); return u;
}
__device__ __forceinline__ void mma8(float c[4], uint32_t a0, uint32_t a1,
                                     uint32_t a2, uint32_t a3,
                                     uint32_t b0, uint32_t b1) {
    asm("mma.sync.aligned.m16n8k8.row.col.f32.tf32.tf32.f32 "
        "{%0,%1,%2,%3}, {%4,%5,%6,%7}, {%8,%9}, {%0,%1,%2,%3};"
        : "+f"(c[0]), "+f"(c[1]), "+f"(c[2]), "+f"(c[3])
        : "r"(a0), "r"(a1), "r"(a2), "r"(a3), "r"(b0), "r"(b1));
}

// ---------------- scratch ----------------
__device__ float g_x1  [MTOT*CCH];
__device__ float g_qkv [MTOT*3*CCH];
__device__ float g_bias[NHEAD*NN];
__device__ float g_attn[MTOT*CCH];
__device__ float g_x3  [MTOT*CCH];
__device__ float g_x4  [MTOT*CCH];
__device__ float g_ffn [MTOT*HID];

// ---------------- bias expand ----------------
__global__ void __launch_bounds__(256) expand_bias_k(
    const float* __restrict__ table, const int* __restrict__ relidx,
    float* __restrict__ biasF)
{
    int t = blockIdx.x * 256 + threadIdx.x;
    int idx = relidx[t];
    #pragma unroll
    for (int h = 0; h < NHEAD; h++)
        biasF[(size_t)h * NN + t] = table[idx * NHEAD + h];
}

// ---------------- block reduction ----------------
__device__ __forceinline__ float block_sum_256(float v, float* sh)
{
    __syncthreads();
    int lane = threadIdx.x & 31, wid = threadIdx.x >> 5;
    #pragma unroll
    for (int o = 16; o; o >>= 1) v += __shfl_xor_sync(0xffffffffu, v, o);
    if (!lane) sh[wid] = v;
    __syncthreads();
    if (threadIdx.x < 8) {
        float t = sh[threadIdx.x];
        #pragma unroll
        for (int o = 4; o; o >>= 1) t += __shfl_xor_sync(0xffu, t, o);
        if (!threadIdx.x) sh[0] = t;
    }
    __syncthreads();
    return sh[0];
}

// ---------------- LayerNorm ----------------
template<int TRANSPOSED>
__global__ void __launch_bounds__(256) ln_k(
    const float* __restrict__ in, const float* __restrict__ w,
    const float* __restrict__ bsh, float* __restrict__ out)
{
    __shared__ float sh[8];
    int token = blockIdx.x;
    int c = threadIdx.x;
    float v;
    if (TRANSPOSED) {
        int bb = token >> 10, p = token & 1023;
        v = in[((size_t)bb * CCH + c) * NTOK + p];
    } else {
        v = in[(size_t)token * CCH + c];
    }
    float mu  = block_sum_256(v, sh) * (1.0f / 256.0f);
    float d   = v - mu;
    float var = block_sum_256(d * d, sh) * (1.0f / 256.0f);
    out[(size_t)token * CCH + c] = d * rsqrtf(var + 1e-5f) * w[c] + bsh[c];
}

// ---------------- tf32 MMA GEMM: 128x128 block, ktile 32, 8 warps 32x64 ----
// As[m][k] stride 36, Bs[n][k] stride 36 (both tf32). Frag loads conflict-free.
template<int EPI>
__global__ void __launch_bounds__(256, 2) gemm_t_k(
    const float* __restrict__ A, const float* __restrict__ Bm,
    const float* __restrict__ bias, float* __restrict__ C,
    int M, int N, int K,
    const float* __restrict__ aux, float* __restrict__ aux2)
{
    __shared__ uint32_t As[128][36];
    __shared__ uint32_t Bs[128][36];

    const int tid  = threadIdx.x;
    const int w    = tid >> 5;
    const int lane = tid & 31;
    const int g    = lane >> 2;
    const int t    = lane & 3;
    const int wm   = w >> 1;         // 0..3
    const int wn   = w & 1;          // 0..1
    const int row0 = blockIdx.y * 128;
    const int col0 = blockIdx.x * 128;

    float acc[2][8][4] = {};

    for (int k0 = 0; k0 < K; k0 += 32) {
        __syncthreads();
        // fill A: 128x32 = 1024 float4
        #pragma unroll
        for (int p = 0; p < 4; p++) {
            int idx = p * 256 + tid;
            int m = idx >> 3, kq = (idx & 7) * 4;
            float4 v = *(const float4*)&A[(size_t)(row0 + m) * K + k0 + kq];
            uint4 u = make_uint4(tf32c(v.x), tf32c(v.y), tf32c(v.z), tf32c(v.w));
            *(uint4*)&As[m][kq] = u;
        }
        // fill B transposed: Bs[n][k]
        #pragma unroll
        for (int p = 0; p < 4; p++) {
            int idx = p * 256 + tid;
            int n = idx & 127, j = idx >> 7;     // j 0..7 -> k-quad
            uint4 u;
            u.x = tf32c(Bm[(size_t)(k0 + j * 4 + 0) * N + col0 + n]);
            u.y = tf32c(Bm[(size_t)(k0 + j * 4 + 1) * N + col0 + n]);
            u.z = tf32c(Bm[(size_t)(k0 + j * 4 + 2) * N + col0 + n]);
            u.w = tf32c(Bm[(size_t)(k0 + j * 4 + 3) * N + col0 + n]);
            *(uint4*)&Bs[n][j * 4] = u;
        }
        __syncthreads();

        #pragma unroll
        for (int k8 = 0; k8 < 4; k8++) {
            int kb = k8 * 8;
            uint32_t a[2][4];
            #pragma unroll
            for (int mf = 0; mf < 2; mf++) {
                int mr = wm * 32 + mf * 16 + g;
                a[mf][0] = As[mr][kb + t];
                a[mf][1] = As[mr + 8][kb + t];
                a[mf][2] = As[mr][kb + t + 4];
                a[mf][3] = As[mr + 8][kb + t + 4];
            }
            #pragma unroll
            for (int nf = 0; nf < 8; nf++) {
                int nc = wn * 64 + nf * 8 + g;
                uint32_t b0 = Bs[nc][kb + t];
                uint32_t b1 = Bs[nc][kb + t + 4];
                mma8(acc[0][nf], a[0][0], a[0][1], a[0][2], a[0][3], b0, b1);
                mma8(acc[1][nf], a[1][0], a[1][1], a[1][2], a[1][3], b0, b1);
            }
        }
    }

    // epilogue: c0:(g,2t) c1:(g,2t+1) c2:(g+8,2t) c3:(g+8,2t+1)
    #pragma unroll
    for (int mf = 0; mf < 2; mf++) {
        #pragma unroll
        for (int nf = 0; nf < 8; nf++) {
            #pragma unroll
            for (int e = 0; e < 4; e++) {
                int m = row0 + wm * 32 + mf * 16 + g + ((e >> 1) ? 8 : 0);
                int n = col0 + wn * 64 + nf * 8 + 2 * t + (e & 1);
                float v = acc[mf][nf][e];
                if (EPI == 0) {
                    C[(size_t)m * N + n] = v;
                } else if (EPI == 1) {
                    int bb2 = m >> 10, p = m & 1023;
                    v += bias[n] + aux[((size_t)bb2 * CCH + n) * NTOK + p];
                    C[(size_t)m * N + n] = v;
                } else if (EPI == 2) {
                    v += bias[n];
                    v = 0.5f * v * (1.0f + erff(v * 0.7071067811865475f));
                    C[(size_t)m * N + n] = v;
                } else {
                    int bb2 = m >> 10, p = m & 1023;
                    v += bias[n] + aux[(size_t)m * CCH + n];
                    aux2[((size_t)bb2 * CCH + n) * NTOK + p] = v;
                }
            }
        }
    }
}

// ---------------- tf32 MMA flash attention ----------------
// Block = (64 queries, h, b). 8 warps: QK role (wq=w&3 q-frag, wk=w>>2 key-half),
// PV role (wq rows, wd=w>>2 dim-half). P staged in smem as tf32.
__global__ void __launch_bounds__(256, 2) attn_k(
    const float* __restrict__ qkv, const float* __restrict__ biasF,
    float* __restrict__ out)
{
    __shared__ uint32_t Qs[64][36];
    __shared__ uint32_t Ks[64][36];
    __shared__ uint32_t Vs[64][40];
    __shared__ uint32_t Ps[64][68];
    __shared__ float    Lp[2][64];

    const int q0 = blockIdx.x * 64;
    const int h  = blockIdx.y;
    const int b  = blockIdx.z;
    const int tid = threadIdx.x;
    const int w = tid >> 5, lane = tid & 31;
    const int g = lane >> 2, t = lane & 3;
    const int wq = w & 3, wk = w >> 2;   // wk doubles as wd for PV

    // fill Q (64x32): 512 float4, 2 per thread
    #pragma unroll
    for (int p = 0; p < 2; p++) {
        int idx = p * 256 + tid;
        int m = idx >> 3, kq = (idx & 7) * 4;
        float4 v = *(const float4*)(qkv + (size_t)(b * NTOK + q0 + m) * 768
                                    + h * 32 + kq);
        *(uint4*)&Qs[m][kq] =
            make_uint4(tf32c(v.x), tf32c(v.y), tf32c(v.z), tf32c(v.w));
    }

    float o[2][4] = {};
    float l0 = 0.0f, l1 = 0.0f;
    const float scale = 0.17677669529663687f;
    const float* bp = biasF + ((size_t)h << 20)
                      + (size_t)(q0 + wq * 16 + g) * NTOK + wk * 32 + 2 * t;

    for (int kt = 0; kt < 16; kt++) {
        __syncthreads();
        // fill K, V
        #pragma unroll
        for (int p = 0; p < 2; p++) {
            int idx = p * 256 + tid;
            int m = idx >> 3, kq = (idx & 7) * 4;
            const float* kp = qkv + (size_t)(b * NTOK + kt * 64 + m) * 768
                              + 256 + h * 32 + kq;
            float4 kv = *(const float4*)kp;
            float4 vv = *(const float4*)(kp + 256);
            *(uint4*)&Ks[m][kq] =
                make_uint4(tf32c(kv.x), tf32c(kv.y), tf32c(kv.z), tf32c(kv.w));
            *(uint4*)&Vs[m][kq] =
                make_uint4(tf32c(vv.x), tf32c(vv.y), tf32c(vv.z), tf32c(vv.w));
        }
        __syncthreads();

        // ---- QK: 16q x 32k per warp ----
        float s[4][4] = {};
        #pragma unroll
        for (int k8 = 0; k8 < 4; k8++) {
            int kb = k8 * 8;
            int ar = wq * 16 + g;
            uint32_t a0 = Qs[ar][kb + t];
            uint32_t a1 = Qs[ar + 8][kb + t];
            uint32_t a2 = Qs[ar][kb + t + 4];
            uint32_t a3 = Qs[ar + 8][kb + t + 4];
            #pragma unroll
            for (int nf = 0; nf < 4; nf++) {
                int kc = wk * 32 + nf * 8 + g;
                mma8(s[nf], a0, a1, a2, a3, Ks[kc][kb + t], Ks[kc][kb + t + 4]);
            }
        }
        // ---- softmax piece: bias + exp, store tf32 P, row sums ----
        float r0 = 0.0f, r1 = 0.0f;
        #pragma unroll
        for (int nf = 0; nf < 4; nf++) {
            float2 bi0 = *(const float2*)(bp + kt * 64 + nf * 8);
            float2 bi1 = *(const float2*)(bp + kt * 64 + nf * 8 + 8 * NTOK);
            float p00 = __expf(fmaf(s[nf][0], scale, bi0.x));
            float p01 = __expf(fmaf(s[nf][1], scale, bi0.y));
            float p10 = __expf(fmaf(s[nf][2], scale, bi1.x));
            float p11 = __expf(fmaf(s[nf][3], scale, bi1.y));
            r0 += p00 + p01;
            r1 += p10 + p11;
            int col = wk * 32 + nf * 8 + 2 * t;
            *(uint2*)&Ps[wq * 16 + g][col]     = make_uint2(tf32c(p00), tf32c(p01));
            *(uint2*)&Ps[wq * 16 + g + 8][col] = make_uint2(tf32c(p10), tf32c(p11));
        }
        r0 += __shfl_xor_sync(0xffffffffu, r0, 1);
        r0 += __shfl_xor_sync(0xffffffffu, r0, 2);
        r1 += __shfl_xor_sync(0xffffffffu, r1, 1);
        r1 += __shfl_xor_sync(0xffffffffu, r1, 2);
        l0 += r0; l1 += r1;
        __syncthreads();

        // ---- PV: 16q x 16d per warp, k = 64 keys ----
        #pragma unroll
        for (int k8 = 0; k8 < 8; k8++) {
            int kb = k8 * 8;
            int pr = wq * 16 + g;
            uint32_t a0 = Ps[pr][kb + t];
            uint32_t a1 = Ps[pr + 8][kb + t];
            uint32_t a2 = Ps[pr][kb + t + 4];
            uint32_t a3 = Ps[pr + 8][kb + t + 4];
            #pragma unroll
            for (int nf = 0; nf < 2; nf++) {
                int vc = wk * 16 + nf * 8 + g;
                mma8(o[nf], a0, a1, a2, a3, Vs[kb + t][vc], Vs[kb + t + 4][vc]);
            }
        }
    }

    // denominators (each (wk,wq) slot written by exactly one warp)
    if (t == 0) {
        Lp[wk][wq * 16 + g]     = l0;
        Lp[wk][wq * 16 + g + 8] = l1;
    }
    __syncthreads();

    #pragma unroll
    for (int nf = 0; nf < 2; nf++) {
        int row = wq * 16 + g;
        int col = wk * 16 + nf * 8 + 2 * t;
        float inv0 = 1.0f / (Lp[0][row] + Lp[1][row]);
        float inv1 = 1.0f / (Lp[0][row + 8] + Lp[1][row + 8]);
        float* op0 = out + (size_t)(b * NTOK + q0 + row) * CCH + h * 32 + col;
        float* op1 = op0 + 8 * CCH;
        *(float2*)op0 = make_float2(o[nf][0] * inv0, o[nf][1] * inv0);
        *(float2*)op1 = make_float2(o[nf][2] * inv1, o[nf][3] * inv1);
    }
}

// ---------------- launch ----------------
extern "C" void kernel_launch(void* const* d_in, const int* in_sizes, int n_in,
                              void* d_out, int out_size)
{
    const float* x       = (const float*)d_in[0];
    const float* qkv_w   = (const float*)d_in[1];
    const float* proj_w  = (const float*)d_in[2];
    const float* proj_b  = (const float*)d_in[3];
    const float* ffn_w1  = (const float*)d_in[4];
    const float* ffn_b1  = (const float*)d_in[5];
    const float* ffn_w2  = (const float*)d_in[6];
    const float* ffn_b2  = (const float*)d_in[7];
    const float* n1w     = (const float*)d_in[8];
    const float* n1b     = (const float*)d_in[9];
    const float* n2w     = (const float*)d_in[10];
    const float* n2b     = (const float*)d_in[11];
    const float* table   = (const float*)d_in[12];
    const int*   relidx  = (const int*)d_in[13];
    float* out = (float*)d_out;

    void *px1, *pqkv, *pbias, *pattn, *px3, *px4, *pffn;
    cudaGetSymbolAddress(&px1,  g_x1);
    cudaGetSymbolAddress(&pqkv, g_qkv);
    cudaGetSymbolAddress(&pbias,g_bias);
    cudaGetSymbolAddress(&pattn,g_attn);
    cudaGetSymbolAddress(&px3,  g_x3);
    cudaGetSymbolAddress(&px4,  g_x4);
    cudaGetSymbolAddress(&pffn, g_ffn);

    expand_bias_k<<<NN / 256, 256>>>(table, relidx, (float*)pbias);
    ln_k<1><<<MTOT, 256>>>(x, n1w, n1b, (float*)px1);
    gemm_t_k<0><<<dim3(768 / 128, MTOT / 128), 256>>>(
        (const float*)px1, qkv_w, nullptr, (float*)pqkv,
        MTOT, 768, 256, nullptr, nullptr);
    attn_k<<<dim3(16, NHEAD, BATCH), 256>>>(
        (const float*)pqkv, (const float*)pbias, (float*)pattn);
    gemm_t_k<1><<<dim3(256 / 128, MTOT / 128), 256>>>(
        (const float*)pattn, proj_w, proj_b, (float*)px3,
        MTOT, 256, 256, x, nullptr);
    ln_k<0><<<MTOT, 256>>>((const float*)px3, n2w, n2b, (float*)px4);
    gemm_t_k<2><<<dim3(HID / 128, MTOT / 128), 256>>>(
        (const float*)px4, ffn_w1, ffn_b1, (float*)pffn,
        MTOT, HID, 256, nullptr, nullptr);
    gemm_t_k<3><<<dim3(256 / 128, MTOT / 128), 256>>>(
        (const float*)pffn, ffn_w2, ffn_b2, nullptr,
        MTOT, 256, 1024, (const float*)px3, out);
}

// round 5
// speedup vs baseline: 4.3997x; 1.2161x over previous
#include <cuda_runtime.h>
#include <math.h>
#include <stdint.h>

#define BATCH 16
#define CCH   256
#define NTOK  1024
#define NN    (1024*1024)
#define NHEAD 8
#define HID   1024
#define MTOT  (BATCH*NTOK)   // 16384

// ---------------- tf32 / mma / cp.async helpers ----------------
__device__ __forceinline__ uint32_t tf32c(float f) {
    uint32_t u; asm("cvt.rna.tf32.f32 %0, %1;" : "=r"(u) : "f"(f)); return u;
}
__device__ __forceinline__ void mma8(float c[4], uint32_t a0, uint32_t a1,
                                     uint32_t a2, uint32_t a3,
                                     uint32_t b0, uint32_t b1) {
    asm("mma.sync.aligned.m16n8k8.row.col.f32.tf32.tf32.f32 "
        "{%0,%1,%2,%3}, {%4,%5,%6,%7}, {%8,%9}, {%0,%1,%2,%3};"
        : "+f"(c[0]), "+f"(c[1]), "+f"(c[2]), "+f"(c[3])
        : "r"(a0), "r"(a1), "r"(a2), "r"(a3), "r"(b0), "r"(b1));
}
__device__ __forceinline__ void cpa16(uint32_t dst, const void* src) {
    asm volatile("cp.async.cg.shared.global [%0], [%1], 16;"
                 :: "r"(dst), "l"(src) : "memory");
}
#define CPC()  asm volatile("cp.async.commit_group;" ::: "memory")
#define CPW1() asm volatile("cp.async.wait_group 1;" ::: "memory")

// ---------------- scratch ----------------
__device__ float g_x1  [MTOT*CCH];
__device__ float g_qkv [MTOT*3*CCH];
__device__ float g_bias[NHEAD*NN];
__device__ float g_attn[MTOT*CCH];
__device__ float g_x3  [MTOT*CCH];
__device__ float g_x4  [MTOT*CCH];
__device__ float g_ffn [MTOT*HID];

// ---------------- bias expand ----------------
__global__ void __launch_bounds__(256) expand_bias_k(
    const float* __restrict__ table, const int* __restrict__ relidx,
    float* __restrict__ biasF)
{
    int t = blockIdx.x * 256 + threadIdx.x;
    int idx = relidx[t];
    #pragma unroll
    for (int h = 0; h < NHEAD; h++)
        biasF[(size_t)h * NN + t] = table[idx * NHEAD + h];
}

// ---------------- block reduction ----------------
__device__ __forceinline__ float block_sum_256(float v, float* sh)
{
    __syncthreads();
    int lane = threadIdx.x & 31, wid = threadIdx.x >> 5;
    #pragma unroll
    for (int o = 16; o; o >>= 1) v += __shfl_xor_sync(0xffffffffu, v, o);
    if (!lane) sh[wid] = v;
    __syncthreads();
    if (threadIdx.x < 8) {
        float t = sh[threadIdx.x];
        #pragma unroll
        for (int o = 4; o; o >>= 1) t += __shfl_xor_sync(0xffu, t, o);
        if (!threadIdx.x) sh[0] = t;
    }
    __syncthreads();
    return sh[0];
}

// ---------------- LayerNorm ----------------
template<int TRANSPOSED>
__global__ void __launch_bounds__(256) ln_k(
    const float* __restrict__ in, const float* __restrict__ w,
    const float* __restrict__ bsh, float* __restrict__ out)
{
    __shared__ float sh[8];
    int token = blockIdx.x;
    int c = threadIdx.x;
    float v;
    if (TRANSPOSED) {
        int bb = token >> 10, p = token & 1023;
        v = in[((size_t)bb * CCH + c) * NTOK + p];
    } else {
        v = in[(size_t)token * CCH + c];
    }
    float mu  = block_sum_256(v, sh) * (1.0f / 256.0f);
    float d   = v - mu;
    float var = block_sum_256(d * d, sh) * (1.0f / 256.0f);
    out[(size_t)token * CCH + c] = d * rsqrtf(var + 1e-5f) * w[c] + bsh[c];
}

// ---------------- tf32 MMA GEMM, cp.async 2-stage pipeline ----------------
// As [m][k] stride 36 (bank 4g+t distinct), Bk [k][n] stride 136 (8t+g distinct)
template<int EPI>
__global__ void __launch_bounds__(256, 2) gemm_t_k(
    const float* __restrict__ A, const float* __restrict__ Bm,
    const float* __restrict__ bias, float* __restrict__ C,
    int M, int N, int K,
    const float* __restrict__ aux, float* __restrict__ aux2)
{
    __shared__ uint32_t As[2 * 128 * 36];
    __shared__ uint32_t Bk[2 * 32 * 136];

    const int tid  = threadIdx.x;
    const int w    = tid >> 5;
    const int lane = tid & 31;
    const int g    = lane >> 2;
    const int t    = lane & 3;
    const int wm   = w >> 1;
    const int wn   = w & 1;
    const int row0 = blockIdx.y * 128;
    const int col0 = blockIdx.x * 128;

    const uint32_t asb = (uint32_t)__cvta_generic_to_shared(As);
    const uint32_t bsb = (uint32_t)__cvta_generic_to_shared(Bk);

    float acc[2][8][4] = {};

    auto loadT = [&](int k0, int s) {
        #pragma unroll
        for (int p = 0; p < 4; p++) {
            int idx = p * 256 + tid;
            int m = idx >> 3, kq = (idx & 7) * 4;
            cpa16(asb + (uint32_t)(s * 4608 + m * 36 + kq) * 4,
                  A + (size_t)(row0 + m) * K + k0 + kq);
        }
        #pragma unroll
        for (int p = 0; p < 4; p++) {
            int idx = p * 256 + tid;
            int kk = idx >> 5, nq = (idx & 31) * 4;
            cpa16(bsb + (uint32_t)(s * 4352 + kk * 136 + nq) * 4,
                  Bm + (size_t)(k0 + kk) * N + col0 + nq);
        }
    };

    const int nk = K / 32;
    loadT(0, 0); CPC();

    for (int kt = 0; kt < nk; kt++) {
        int s = kt & 1;
        if (kt + 1 < nk) loadT((kt + 1) * 32, s ^ 1);
        CPC(); CPW1();
        __syncthreads();
        const uint32_t* as = As + s * 4608;
        const uint32_t* bs = Bk + s * 4352;
        #pragma unroll
        for (int k8 = 0; k8 < 4; k8++) {
            int kb = k8 * 8;
            uint32_t a[2][4];
            #pragma unroll
            for (int mf = 0; mf < 2; mf++) {
                int mr = wm * 32 + mf * 16 + g;
                a[mf][0] = as[mr * 36 + kb + t];
                a[mf][1] = as[(mr + 8) * 36 + kb + t];
                a[mf][2] = as[mr * 36 + kb + t + 4];
                a[mf][3] = as[(mr + 8) * 36 + kb + t + 4];
            }
            #pragma unroll
            for (int nf = 0; nf < 8; nf++) {
                int nc = wn * 64 + nf * 8 + g;
                uint32_t b0 = bs[(kb + t) * 136 + nc];
                uint32_t b1 = bs[(kb + t + 4) * 136 + nc];
                mma8(acc[0][nf], a[0][0], a[0][1], a[0][2], a[0][3], b0, b1);
                mma8(acc[1][nf], a[1][0], a[1][1], a[1][2], a[1][3], b0, b1);
            }
        }
        __syncthreads();
    }

    #pragma unroll
    for (int mf = 0; mf < 2; mf++) {
        #pragma unroll
        for (int nf = 0; nf < 8; nf++) {
            #pragma unroll
            for (int e = 0; e < 4; e++) {
                int m = row0 + wm * 32 + mf * 16 + g + ((e >> 1) ? 8 : 0);
                int n = col0 + wn * 64 + nf * 8 + 2 * t + (e & 1);
                float v = acc[mf][nf][e];
                if (EPI == 0) {
                    C[(size_t)m * N + n] = v;
                } else if (EPI == 1) {
                    int bb2 = m >> 10, p = m & 1023;
                    v += bias[n] + aux[((size_t)bb2 * CCH + n) * NTOK + p];
                    C[(size_t)m * N + n] = v;
                } else if (EPI == 2) {
                    v += bias[n];
                    v = 0.5f * v * (1.0f + erff(v * 0.7071067811865475f));
                    C[(size_t)m * N + n] = v;
                } else {
                    int bb2 = m >> 10, p = m & 1023;
                    v += bias[n] + aux[(size_t)m * CCH + n];
                    aux2[((size_t)bb2 * CCH + n) * NTOK + p] = v;
                }
            }
        }
    }
}

// ---------------- tf32 MMA flash attention, cp.async K/V pipeline ----------
__global__ void __launch_bounds__(256, 2) attn_k(
    const float* __restrict__ qkv, const float* __restrict__ biasF,
    float* __restrict__ out)
{
    __shared__ uint32_t Qs[64 * 36];
    __shared__ uint32_t Ks[2 * 64 * 36];
    __shared__ uint32_t Vs[2 * 64 * 40];
    __shared__ uint32_t Ps[64 * 68];
    __shared__ float    Lp[2][64];

    const int q0 = blockIdx.x * 64;
    const int h  = blockIdx.y;
    const int b  = blockIdx.z;
    const int tid = threadIdx.x;
    const int w = tid >> 5, lane = tid & 31;
    const int g = lane >> 2, t = lane & 3;
    const int wq = w & 3, wk = w >> 2;

    const uint32_t ksb = (uint32_t)__cvta_generic_to_shared(Ks);
    const uint32_t vsb = (uint32_t)__cvta_generic_to_shared(Vs);

    auto ldkv = [&](int kt, int s) {
        #pragma unroll
        for (int p = 0; p < 2; p++) {
            int idx = p * 256 + tid;
            int m = idx >> 3, kq = (idx & 7) * 4;
            const float* kp = qkv + (size_t)(b * NTOK + kt * 64 + m) * 768
                              + 256 + h * 32 + kq;
            cpa16(ksb + (uint32_t)(s * 2304 + m * 36 + kq) * 4, kp);
            cpa16(vsb + (uint32_t)(s * 2560 + m * 40 + kq) * 4, kp + 256);
        }
    };
    ldkv(0, 0); CPC();

    // Q fill (raw fp32 bits; tensor HW truncates to tf32)
    #pragma unroll
    for (int p = 0; p < 2; p++) {
        int idx = p * 256 + tid;
        int m = idx >> 3, kq = (idx & 7) * 4;
        float4 v = *(const float4*)(qkv + (size_t)(b * NTOK + q0 + m) * 768
                                    + h * 32 + kq);
        *(uint4*)&Qs[m * 36 + kq] = make_uint4(
            __float_as_uint(v.x), __float_as_uint(v.y),
            __float_as_uint(v.z), __float_as_uint(v.w));
    }

    float o[2][4] = {};
    float l0 = 0.0f, l1 = 0.0f;
    const float scale = 0.17677669529663687f;
    const float* bp = biasF + ((size_t)h << 20)
                      + (size_t)(q0 + wq * 16 + g) * NTOK + wk * 32 + 2 * t;

    float2 ba[4], bb[4];
    #pragma unroll
    for (int nf = 0; nf < 4; nf++) {
        ba[nf] = *(const float2*)(bp + nf * 8);
        bb[nf] = *(const float2*)(bp + nf * 8 + 8 * NTOK);
    }

    for (int kt = 0; kt < 16; kt++) {
        int s = kt & 1;
        __syncthreads();                 // prev PV done: Ps free, Vs[s^1] free
        if (kt < 15) ldkv(kt + 1, s ^ 1);
        CPC(); CPW1();
        __syncthreads();                 // KV(kt) landed
        const uint32_t* ks = Ks + s * 2304;
        const uint32_t* vs = Vs + s * 2560;

        // ---- QK: 16q x 32k per warp ----
        float sc[4][4] = {};
        #pragma unroll
        for (int k8 = 0; k8 < 4; k8++) {
            int kb = k8 * 8, ar = wq * 16 + g;
            uint32_t a0 = Qs[ar * 36 + kb + t];
            uint32_t a1 = Qs[(ar + 8) * 36 + kb + t];
            uint32_t a2 = Qs[ar * 36 + kb + t + 4];
            uint32_t a3 = Qs[(ar + 8) * 36 + kb + t + 4];
            #pragma unroll
            for (int nf = 0; nf < 4; nf++) {
                int kc = wk * 32 + nf * 8 + g;
                mma8(sc[nf], a0, a1, a2, a3,
                     ks[kc * 36 + kb + t], ks[kc * 36 + kb + t + 4]);
            }
        }

        // ---- softmax piece (denominator from rounded P for consistency) ----
        float r0 = 0.0f, r1 = 0.0f;
        #pragma unroll
        for (int nf = 0; nf < 4; nf++) {
            float p00 = __expf(fmaf(sc[nf][0], scale, ba[nf].x));
            float p01 = __expf(fmaf(sc[nf][1], scale, ba[nf].y));
            float p10 = __expf(fmaf(sc[nf][2], scale, bb[nf].x));
            float p11 = __expf(fmaf(sc[nf][3], scale, bb[nf].y));
            uint32_t u00 = tf32c(p00), u01 = tf32c(p01);
            uint32_t u10 = tf32c(p10), u11 = tf32c(p11);
            r0 += __uint_as_float(u00) + __uint_as_float(u01);
            r1 += __uint_as_float(u10) + __uint_as_float(u11);
            int col = wk * 32 + nf * 8 + 2 * t;
            *(uint2*)&Ps[(wq * 16 + g) * 68 + col]     = make_uint2(u00, u01);
            *(uint2*)&Ps[(wq * 16 + g + 8) * 68 + col] = make_uint2(u10, u11);
        }
        // rotate bias prefetch for next tile
        if (kt < 15) {
            const float* bq = bp + (kt + 1) * 64;
            #pragma unroll
            for (int nf = 0; nf < 4; nf++) {
                ba[nf] = *(const float2*)(bq + nf * 8);
                bb[nf] = *(const float2*)(bq + nf * 8 + 8 * NTOK);
            }
        }
        r0 += __shfl_xor_sync(0xffffffffu, r0, 1);
        r0 += __shfl_xor_sync(0xffffffffu, r0, 2);
        r1 += __shfl_xor_sync(0xffffffffu, r1, 1);
        r1 += __shfl_xor_sync(0xffffffffu, r1, 2);
        l0 += r0; l1 += r1;
        __syncthreads();                 // Ps visible to all warps

        // ---- PV: 16q x 16d per warp over 64 keys ----
        #pragma unroll
        for (int k8 = 0; k8 < 8; k8++) {
            int kb = k8 * 8, pr = wq * 16 + g;
            uint32_t a0 = Ps[pr * 68 + kb + t];
            uint32_t a1 = Ps[(pr + 8) * 68 + kb + t];
            uint32_t a2 = Ps[pr * 68 + kb + t + 4];
            uint32_t a3 = Ps[(pr + 8) * 68 + kb + t + 4];
            #pragma unroll
            for (int nf = 0; nf < 2; nf++) {
                int vc = wk * 16 + nf * 8 + g;
                mma8(o[nf], a0, a1, a2, a3,
                     vs[(kb + t) * 40 + vc], vs[(kb + t + 4) * 40 + vc]);
            }
        }
    }

    if (t == 0) {
        Lp[wk][wq * 16 + g]     = l0;
        Lp[wk][wq * 16 + g + 8] = l1;
    }
    __syncthreads();

    #pragma unroll
    for (int nf = 0; nf < 2; nf++) {
        int row = wq * 16 + g;
        int col = wk * 16 + nf * 8 + 2 * t;
        float inv0 = 1.0f / (Lp[0][row] + Lp[1][row]);
        float inv1 = 1.0f / (Lp[0][row + 8] + Lp[1][row + 8]);
        float* op0 = out + (size_t)(b * NTOK + q0 + row) * CCH + h * 32 + col;
        float* op1 = op0 + 8 * CCH;
        *(float2*)op0 = make_float2(o[nf][0] * inv0, o[nf][1] * inv0);
        *(float2*)op1 = make_float2(o[nf][2] * inv1, o[nf][3] * inv1);
    }
}

// ---------------- launch ----------------
extern "C" void kernel_launch(void* const* d_in, const int* in_sizes, int n_in,
                              void* d_out, int out_size)
{
    const float* x       = (const float*)d_in[0];
    const float* qkv_w   = (const float*)d_in[1];
    const float* proj_w  = (const float*)d_in[2];
    const float* proj_b  = (const float*)d_in[3];
    const float* ffn_w1  = (const float*)d_in[4];
    const float* ffn_b1  = (const float*)d_in[5];
    const float* ffn_w2  = (const float*)d_in[6];
    const float* ffn_b2  = (const float*)d_in[7];
    const float* n1w     = (const float*)d_in[8];
    const float* n1b     = (const float*)d_in[9];
    const float* n2w     = (const float*)d_in[10];
    const float* n2b     = (const float*)d_in[11];
    const float* table   = (const float*)d_in[12];
    const int*   relidx  = (const int*)d_in[13];
    float* out = (float*)d_out;

    void *px1, *pqkv, *pbias, *pattn, *px3, *px4, *pffn;
    cudaGetSymbolAddress(&px1,  g_x1);
    cudaGetSymbolAddress(&pqkv, g_qkv);
    cudaGetSymbolAddress(&pbias,g_bias);
    cudaGetSymbolAddress(&pattn,g_attn);
    cudaGetSymbolAddress(&px3,  g_x3);
    cudaGetSymbolAddress(&px4,  g_x4);
    cudaGetSymbolAddress(&pffn, g_ffn);

    expand_bias_k<<<NN / 256, 256>>>(table, relidx, (float*)pbias);
    ln_k<1><<<MTOT, 256>>>(x, n1w, n1b, (float*)px1);
    gemm_t_k<0><<<dim3(768 / 128, MTOT / 128), 256>>>(
        (const float*)px1, qkv_w, nullptr, (float*)pqkv,
        MTOT, 768, 256, nullptr, nullptr);
    attn_k<<<dim3(16, NHEAD, BATCH), 256>>>(
        (const float*)pqkv, (const float*)pbias, (float*)pattn);
    gemm_t_k<1><<<dim3(256 / 128, MTOT / 128), 256>>>(
        (const float*)pattn, proj_w, proj_b, (float*)px3,
        MTOT, 256, 256, x, nullptr);
    ln_k<0><<<MTOT, 256>>>((const float*)px3, n2w, n2b, (float*)px4);
    gemm_t_k<2><<<dim3(HID / 128, MTOT / 128), 256>>>(
        (const float*)px4, ffn_w1, ffn_b1, (float*)pffn,
        MTOT, HID, 256, nullptr, nullptr);
    gemm_t_k<3><<<dim3(256 / 128, MTOT / 128), 256>>>(
        (const float*)pffn, ffn_w2, ffn_b2, nullptr,
        MTOT, 256, 1024, (const float*)px3, out);
}

// round 6
// speedup vs baseline: 5.2341x; 1.1897x over previous
#include <cuda_runtime.h>
#include <math.h>
#include <stdint.h>

#define BATCH 16
#define CCH   256
#define NTOK  1024
#define NN    (1024*1024)
#define NHEAD 8
#define HID   1024
#define MTOT  (BATCH*NTOK)   // 16384

// ---------------- tf32 / mma / cp.async helpers ----------------
__device__ __forceinline__ uint32_t tf32c(float f) {
    uint32_t u; asm("cvt.rna.tf32.f32 %0, %1;" : "=r"(u) : "f"(f)); return u;
}
__device__ __forceinline__ float tf32trunc(float f) {
    return __uint_as_float(__float_as_uint(f) & 0xffffe000u);
}
__device__ __forceinline__ void mma8(float c[4], uint32_t a0, uint32_t a1,
                                     uint32_t a2, uint32_t a3,
                                     uint32_t b0, uint32_t b1) {
    asm("mma.sync.aligned.m16n8k8.row.col.f32.tf32.tf32.f32 "
        "{%0,%1,%2,%3}, {%4,%5,%6,%7}, {%8,%9}, {%0,%1,%2,%3};"
        : "+f"(c[0]), "+f"(c[1]), "+f"(c[2]), "+f"(c[3])
        : "r"(a0), "r"(a1), "r"(a2), "r"(a3), "r"(b0), "r"(b1));
}
__device__ __forceinline__ void cpa16(uint32_t dst, const void* src) {
    asm volatile("cp.async.cg.shared.global [%0], [%1], 16;"
                 :: "r"(dst), "l"(src) : "memory");
}
#define CPC()  asm volatile("cp.async.commit_group;" ::: "memory")
#define CPW1() asm volatile("cp.async.wait_group 1;" ::: "memory")
#define CPW0() asm volatile("cp.async.wait_group 0;" ::: "memory")

// ---------------- scratch ----------------
__device__ float g_x1  [MTOT*CCH];
__device__ float g_qkv [MTOT*3*CCH];
__device__ float g_bias[NHEAD*NN];
__device__ float g_attn[MTOT*CCH];
__device__ float g_x3  [MTOT*CCH];
__device__ float g_x4  [MTOT*CCH];
__device__ float g_ffn [MTOT*HID];

// ---------------- bias expand ----------------
__global__ void __launch_bounds__(256) expand_bias_k(
    const float* __restrict__ table, const int* __restrict__ relidx,
    float* __restrict__ biasF)
{
    int t = blockIdx.x * 256 + threadIdx.x;
    int idx = relidx[t];
    #pragma unroll
    for (int h = 0; h < NHEAD; h++)
        biasF[(size_t)h * NN + t] = table[idx * NHEAD + h];
}

// ---------------- block reduction ----------------
__device__ __forceinline__ float block_sum_256(float v, float* sh)
{
    __syncthreads();
    int lane = threadIdx.x & 31, wid = threadIdx.x >> 5;
    #pragma unroll
    for (int o = 16; o; o >>= 1) v += __shfl_xor_sync(0xffffffffu, v, o);
    if (!lane) sh[wid] = v;
    __syncthreads();
    if (threadIdx.x < 8) {
        float t = sh[threadIdx.x];
        #pragma unroll
        for (int o = 4; o; o >>= 1) t += __shfl_xor_sync(0xffu, t, o);
        if (!threadIdx.x) sh[0] = t;
    }
    __syncthreads();
    return sh[0];
}

// ---------------- LayerNorm ----------------
template<int TRANSPOSED>
__global__ void __launch_bounds__(256) ln_k(
    const float* __restrict__ in, const float* __restrict__ w,
    const float* __restrict__ bsh, float* __restrict__ out)
{
    __shared__ float sh[8];
    int token = blockIdx.x;
    int c = threadIdx.x;
    float v;
    if (TRANSPOSED) {
        int bb = token >> 10, p = token & 1023;
        v = in[((size_t)bb * CCH + c) * NTOK + p];
    } else {
        v = in[(size_t)token * CCH + c];
    }
    float mu  = block_sum_256(v, sh) * (1.0f / 256.0f);
    float d   = v - mu;
    float var = block_sum_256(d * d, sh) * (1.0f / 256.0f);
    out[(size_t)token * CCH + c] = d * rsqrtf(var + 1e-5f) * w[c] + bsh[c];
}

// ---------------- tf32 MMA GEMM, cp.async 2-stage pipeline (from R5) --------
template<int EPI>
__global__ void __launch_bounds__(256, 2) gemm_t_k(
    const float* __restrict__ A, const float* __restrict__ Bm,
    const float* __restrict__ bias, float* __restrict__ C,
    int M, int N, int K,
    const float* __restrict__ aux, float* __restrict__ aux2)
{
    __shared__ uint32_t As[2 * 128 * 36];
    __shared__ uint32_t Bk[2 * 32 * 136];

    const int tid  = threadIdx.x;
    const int w    = tid >> 5;
    const int lane = tid & 31;
    const int g    = lane >> 2;
    const int t    = lane & 3;
    const int wm   = w >> 1;
    const int wn   = w & 1;
    const int row0 = blockIdx.y * 128;
    const int col0 = blockIdx.x * 128;

    const uint32_t asb = (uint32_t)__cvta_generic_to_shared(As);
    const uint32_t bsb = (uint32_t)__cvta_generic_to_shared(Bk);

    float acc[2][8][4] = {};

    auto loadT = [&](int k0, int s) {
        #pragma unroll
        for (int p = 0; p < 4; p++) {
            int idx = p * 256 + tid;
            int m = idx >> 3, kq = (idx & 7) * 4;
            cpa16(asb + (uint32_t)(s * 4608 + m * 36 + kq) * 4,
                  A + (size_t)(row0 + m) * K + k0 + kq);
        }
        #pragma unroll
        for (int p = 0; p < 4; p++) {
            int idx = p * 256 + tid;
            int kk = idx >> 5, nq = (idx & 31) * 4;
            cpa16(bsb + (uint32_t)(s * 4352 + kk * 136 + nq) * 4,
                  Bm + (size_t)(k0 + kk) * N + col0 + nq);
        }
    };

    const int nk = K / 32;
    loadT(0, 0); CPC();

    for (int kt = 0; kt < nk; kt++) {
        int s = kt & 1;
        if (kt + 1 < nk) loadT((kt + 1) * 32, s ^ 1);
        CPC(); CPW1();
        __syncthreads();
        const uint32_t* as = As + s * 4608;
        const uint32_t* bs = Bk + s * 4352;
        #pragma unroll
        for (int k8 = 0; k8 < 4; k8++) {
            int kb = k8 * 8;
            uint32_t a[2][4];
            #pragma unroll
            for (int mf = 0; mf < 2; mf++) {
                int mr = wm * 32 + mf * 16 + g;
                a[mf][0] = as[mr * 36 + kb + t];
                a[mf][1] = as[(mr + 8) * 36 + kb + t];
                a[mf][2] = as[mr * 36 + kb + t + 4];
                a[mf][3] = as[(mr + 8) * 36 + kb + t + 4];
            }
            #pragma unroll
            for (int nf = 0; nf < 8; nf++) {
                int nc = wn * 64 + nf * 8 + g;
                uint32_t b0 = bs[(kb + t) * 136 + nc];
                uint32_t b1 = bs[(kb + t + 4) * 136 + nc];
                mma8(acc[0][nf], a[0][0], a[0][1], a[0][2], a[0][3], b0, b1);
                mma8(acc[1][nf], a[1][0], a[1][1], a[1][2], a[1][3], b0, b1);
            }
        }
        __syncthreads();
    }

    #pragma unroll
    for (int mf = 0; mf < 2; mf++) {
        #pragma unroll
        for (int nf = 0; nf < 8; nf++) {
            #pragma unroll
            for (int e = 0; e < 4; e++) {
                int m = row0 + wm * 32 + mf * 16 + g + ((e >> 1) ? 8 : 0);
                int n = col0 + wn * 64 + nf * 8 + 2 * t + (e & 1);
                float v = acc[mf][nf][e];
                if (EPI == 0) {
                    C[(size_t)m * N + n] = v;
                } else if (EPI == 1) {
                    int bb2 = m >> 10, p = m & 1023;
                    v += bias[n] + aux[((size_t)bb2 * CCH + n) * NTOK + p];
                    C[(size_t)m * N + n] = v;
                } else if (EPI == 2) {
                    v += bias[n];
                    v = 0.5f * v * (1.0f + erff(v * 0.7071067811865475f));
                    C[(size_t)m * N + n] = v;
                } else {
                    int bb2 = m >> 10, p = m & 1023;
                    v += bias[n] + aux[(size_t)m * CCH + n];
                    aux2[((size_t)bb2 * CCH + n) * NTOK + p] = v;
                }
            }
        }
    }
}

// ---------------- tf32 MMA flash attention, P-in-register, 3-stage ring ----
// Block = 128 queries x (h,b). Warp w owns q rows 16w..16w+15, all 64 keys.
// V smem rows permuted (even keys -> slots 0-3, odd -> 4-7 per 8-group) so the
// QK C-fragment feeds the PV A-fragment directly from registers.
__global__ void __launch_bounds__(256, 2) attn_k(
    const float* __restrict__ qkv, const float* __restrict__ biasF,
    float* __restrict__ out)
{
    __shared__ uint32_t Ks[3][64 * 36];
    __shared__ uint32_t Vs[3][64 * 40];

    const int q0 = blockIdx.x * 128;
    const int h  = blockIdx.y;
    const int b  = blockIdx.z;
    const int tid = threadIdx.x;
    const int w = tid >> 5, lane = tid & 31;
    const int g = lane >> 2, t = lane & 3;

    const uint32_t ksb = (uint32_t)__cvta_generic_to_shared(Ks);
    const uint32_t vsb = (uint32_t)__cvta_generic_to_shared(Vs);

    auto ldkv = [&](int kt, int s) {
        #pragma unroll
        for (int p = 0; p < 2; p++) {
            int idx = p * 256 + tid;
            int m = idx >> 3, kq = (idx & 7) * 4;
            const float* kp = qkv + (size_t)(b * NTOK + kt * 64 + m) * 768
                              + 256 + h * 32 + kq;
            cpa16(ksb + (uint32_t)(s * 2304 + m * 36 + kq) * 4, kp);
            int vslot = (m & ~7) | ((m & 7) >> 1) | ((m & 1) << 2);
            cpa16(vsb + (uint32_t)(s * 2560 + vslot * 40 + kq) * 4, kp + 256);
        }
    };

    ldkv(0, 0); CPC();
    ldkv(1, 1); CPC();

    // Q fragments hoisted into registers (loop-invariant)
    uint32_t qf[4][4];
    {
        const float* qp = qkv + (size_t)(b * NTOK + q0 + w * 16) * 768 + h * 32;
        #pragma unroll
        for (int k8 = 0; k8 < 4; k8++) {
            int kb = k8 * 8;
            qf[k8][0] = __float_as_uint(qp[(size_t)g * 768 + kb + t]);
            qf[k8][1] = __float_as_uint(qp[(size_t)(g + 8) * 768 + kb + t]);
            qf[k8][2] = __float_as_uint(qp[(size_t)g * 768 + kb + t + 4]);
            qf[k8][3] = __float_as_uint(qp[(size_t)(g + 8) * 768 + kb + t + 4]);
        }
    }

    float o[4][4] = {};
    float l0 = 0.0f, l1 = 0.0f;
    const float scale = 0.17677669529663687f;
    const float* bbase = biasF + ((size_t)h << 20)
                         + (size_t)(q0 + w * 16 + g) * NTOK + 2 * t;

    for (int kt = 0; kt < 16; kt++) {
        int s = kt % 3;
        if (kt < 15) { CPW1(); } else { CPW0(); }
        __syncthreads();
        if (kt + 2 < 16) { ldkv(kt + 2, (kt + 2) % 3); CPC(); }
        const uint32_t* ks = Ks[s];
        const uint32_t* vs = Vs[s];

        // ---- QK: 16q x 64k per warp, Q from registers ----
        float c[8][4] = {};
        #pragma unroll
        for (int k8 = 0; k8 < 4; k8++) {
            int kb = k8 * 8;
            #pragma unroll
            for (int nf = 0; nf < 8; nf++) {
                int kc = nf * 8 + g;
                mma8(c[nf], qf[k8][0], qf[k8][1], qf[k8][2], qf[k8][3],
                     ks[kc * 36 + kb + t], ks[kc * 36 + kb + t + 4]);
            }
        }

        // ---- softmax piece: bias + exp + tf32 truncation (consistent) ----
        const float* bp = bbase + kt * 64;
        float r0 = 0.0f, r1 = 0.0f;
        #pragma unroll
        for (int nf = 0; nf < 8; nf++) {
            float2 bA = *(const float2*)(bp + nf * 8);
            float2 bB = *(const float2*)(bp + 8 * NTOK + nf * 8);
            c[nf][0] = tf32trunc(__expf(fmaf(c[nf][0], scale, bA.x)));
            c[nf][1] = tf32trunc(__expf(fmaf(c[nf][1], scale, bA.y)));
            c[nf][2] = tf32trunc(__expf(fmaf(c[nf][2], scale, bB.x)));
            c[nf][3] = tf32trunc(__expf(fmaf(c[nf][3], scale, bB.y)));
            r0 += c[nf][0] + c[nf][1];
            r1 += c[nf][2] + c[nf][3];
        }
        r0 += __shfl_xor_sync(0xffffffffu, r0, 1);
        r0 += __shfl_xor_sync(0xffffffffu, r0, 2);
        r1 += __shfl_xor_sync(0xffffffffu, r1, 1);
        r1 += __shfl_xor_sync(0xffffffffu, r1, 2);
        l0 += r0; l1 += r1;

        // ---- PV: P straight from registers, V rows pre-permuted ----
        #pragma unroll
        for (int j = 0; j < 8; j++) {
            uint32_t a0 = __float_as_uint(c[j][0]);
            uint32_t a1 = __float_as_uint(c[j][2]);
            uint32_t a2 = __float_as_uint(c[j][1]);
            uint32_t a3 = __float_as_uint(c[j][3]);
            #pragma unroll
            for (int dn = 0; dn < 4; dn++) {
                mma8(o[dn], a0, a1, a2, a3,
                     vs[(j * 8 + t) * 40 + dn * 8 + g],
                     vs[(j * 8 + t + 4) * 40 + dn * 8 + g]);
            }
        }
    }

    float inv0 = 1.0f / l0, inv1 = 1.0f / l1;
    float* op = out + (size_t)(b * NTOK + q0 + w * 16 + g) * CCH + h * 32;
    #pragma unroll
    for (int dn = 0; dn < 4; dn++) {
        *(float2*)(op + dn * 8 + 2 * t) =
            make_float2(o[dn][0] * inv0, o[dn][1] * inv0);
        *(float2*)(op + 8 * CCH + dn * 8 + 2 * t) =
            make_float2(o[dn][2] * inv1, o[dn][3] * inv1);
    }
}

// ---------------- launch ----------------
extern "C" void kernel_launch(void* const* d_in, const int* in_sizes, int n_in,
                              void* d_out, int out_size)
{
    const float* x       = (const float*)d_in[0];
    const float* qkv_w   = (const float*)d_in[1];
    const float* proj_w  = (const float*)d_in[2];
    const float* proj_b  = (const float*)d_in[3];
    const float* ffn_w1  = (const float*)d_in[4];
    const float* ffn_b1  = (const float*)d_in[5];
    const float* ffn_w2  = (const float*)d_in[6];
    const float* ffn_b2  = (const float*)d_in[7];
    const float* n1w     = (const float*)d_in[8];
    const float* n1b     = (const float*)d_in[9];
    const float* n2w     = (const float*)d_in[10];
    const float* n2b     = (const float*)d_in[11];
    const float* table   = (const float*)d_in[12];
    const int*   relidx  = (const int*)d_in[13];
    float* out = (float*)d_out;

    void *px1, *pqkv, *pbias, *pattn, *px3, *px4, *pffn;
    cudaGetSymbolAddress(&px1,  g_x1);
    cudaGetSymbolAddress(&pqkv, g_qkv);
    cudaGetSymbolAddress(&pbias,g_bias);
    cudaGetSymbolAddress(&pattn,g_attn);
    cudaGetSymbolAddress(&px3,  g_x3);
    cudaGetSymbolAddress(&px4,  g_x4);
    cudaGetSymbolAddress(&pffn, g_ffn);

    expand_bias_k<<<NN / 256, 256>>>(table, relidx, (float*)pbias);
    ln_k<1><<<MTOT, 256>>>(x, n1w, n1b, (float*)px1);
    gemm_t_k<0><<<dim3(768 / 128, MTOT / 128), 256>>>(
        (const float*)px1, qkv_w, nullptr, (float*)pqkv,
        MTOT, 768, 256, nullptr, nullptr);
    attn_k<<<dim3(NTOK / 128, NHEAD, BATCH), 256>>>(
        (const float*)pqkv, (const float*)pbias, (float*)pattn);
    gemm_t_k<1><<<dim3(256 / 128, MTOT / 128), 256>>>(
        (const float*)pattn, proj_w, proj_b, (float*)px3,
        MTOT, 256, 256, x, nullptr);
    ln_k<0><<<MTOT, 256>>>((const float*)px3, n2w, n2b, (float*)px4);
    gemm_t_k<2><<<dim3(HID / 128, MTOT / 128), 256>>>(
        (const float*)px4, ffn_w1, ffn_b1, (float*)pffn,
        MTOT, HID, 256, nullptr, nullptr);
    gemm_t_k<3><<<dim3(256 / 128, MTOT / 128), 256>>>(
        (const float*)pffn, ffn_w2, ffn_b2, nullptr,
        MTOT, 256, 1024, (const float*)px3, out);
}

// round 7
// speedup vs baseline: 5.8495x; 1.1176x over previous
#include <cuda_runtime.h>
#include <cuda_bf16.h>
#include <math.h>
#include <stdint.h>

#define BATCH 16
#define CCH   256
#define NTOK  1024
#define NN    (1024*1024)
#define NHEAD 8
#define HID   1024
#define MTOT  (BATCH*NTOK)   // 16384

// ---------------- helpers ----------------
__device__ __forceinline__ float tf32trunc(float f) {
    return __uint_as_float(__float_as_uint(f) & 0xffffe000u);
}
__device__ __forceinline__ void mma8(float c[4], uint32_t a0, uint32_t a1,
                                     uint32_t a2, uint32_t a3,
                                     uint32_t b0, uint32_t b1) {
    asm("mma.sync.aligned.m16n8k8.row.col.f32.tf32.tf32.f32 "
        "{%0,%1,%2,%3}, {%4,%5,%6,%7}, {%8,%9}, {%0,%1,%2,%3};"
        : "+f"(c[0]), "+f"(c[1]), "+f"(c[2]), "+f"(c[3])
        : "r"(a0), "r"(a1), "r"(a2), "r"(a3), "r"(b0), "r"(b1));
}
__device__ __forceinline__ void mma16b(float c[4], uint32_t a0, uint32_t a1,
                                       uint32_t a2, uint32_t a3,
                                       uint32_t b0, uint32_t b1) {
    asm("mma.sync.aligned.m16n8k16.row.col.f32.bf16.bf16.f32 "
        "{%0,%1,%2,%3}, {%4,%5,%6,%7}, {%8,%9}, {%0,%1,%2,%3};"
        : "+f"(c[0]), "+f"(c[1]), "+f"(c[2]), "+f"(c[3])
        : "r"(a0), "r"(a1), "r"(a2), "r"(a3), "r"(b0), "r"(b1));
}
__device__ __forceinline__ uint32_t bf16pk(float lo, float hi) {
    uint32_t r;
    asm("cvt.rn.bf16x2.f32 %0, %1, %2;" : "=r"(r) : "f"(hi), "f"(lo));
    return r;
}
__device__ __forceinline__ void cpa16(uint32_t dst, const void* src) {
    asm volatile("cp.async.cg.shared.global [%0], [%1], 16;"
                 :: "r"(dst), "l"(src) : "memory");
}
#define CPC()  asm volatile("cp.async.commit_group;" ::: "memory")
#define CPW1() asm volatile("cp.async.wait_group 1;" ::: "memory")
#define CPW0() asm volatile("cp.async.wait_group 0;" ::: "memory")

// ---------------- scratch ----------------
__device__ float    g_x1  [MTOT*CCH];
__device__ float    g_qkv [MTOT*3*CCH];
__device__ float    g_bias[NHEAD*NN];
__device__ float    g_attn[MTOT*CCH];
__device__ float    g_x3  [MTOT*CCH];
__device__ uint32_t g_x4b [MTOT*CCH/2];     // bf16x2 LN2 out
__device__ uint32_t g_ffnb[MTOT*HID/2];     // bf16x2 gelu out
__device__ uint32_t g_w1p [(CCH/2)*HID];    // w1 k-paired bf16x2
__device__ uint32_t g_w2p [(HID/2)*CCH];    // w2 k-paired bf16x2

// ---------------- weight convert: fp32 [K][N] -> bf16x2-paired [K/2][N] -----
__global__ void __launch_bounds__(256) wcvt_k(
    const float* __restrict__ w, uint32_t* __restrict__ wp, int K2, int N)
{
    int i = blockIdx.x * 256 + threadIdx.x;
    if (i >= K2 * N) return;
    int k2 = i / N, n = i - k2 * N;
    wp[i] = bf16pk(w[(size_t)(2 * k2) * N + n], w[(size_t)(2 * k2 + 1) * N + n]);
}

// ---------------- bias expand ----------------
__global__ void __launch_bounds__(256) expand_bias_k(
    const float* __restrict__ table, const int* __restrict__ relidx,
    float* __restrict__ biasF)
{
    int t = blockIdx.x * 256 + threadIdx.x;
    int idx = relidx[t];
    #pragma unroll
    for (int h = 0; h < NHEAD; h++)
        biasF[(size_t)h * NN + t] = table[idx * NHEAD + h];
}

// ---------------- block reduction ----------------
__device__ __forceinline__ float block_sum_256(float v, float* sh)
{
    __syncthreads();
    int lane = threadIdx.x & 31, wid = threadIdx.x >> 5;
    #pragma unroll
    for (int o = 16; o; o >>= 1) v += __shfl_xor_sync(0xffffffffu, v, o);
    if (!lane) sh[wid] = v;
    __syncthreads();
    if (threadIdx.x < 8) {
        float t = sh[threadIdx.x];
        #pragma unroll
        for (int o = 4; o; o >>= 1) t += __shfl_xor_sync(0xffu, t, o);
        if (!threadIdx.x) sh[0] = t;
    }
    __syncthreads();
    return sh[0];
}

// ---------------- LayerNorm ----------------
template<int TRANSPOSED, int BF16OUT>
__global__ void __launch_bounds__(256) ln_k(
    const float* __restrict__ in, const float* __restrict__ w,
    const float* __restrict__ bsh, void* __restrict__ outv)
{
    __shared__ float sh[8];
    int token = blockIdx.x;
    int c = threadIdx.x;
    float v;
    if (TRANSPOSED) {
        int bb = token >> 10, p = token & 1023;
        v = in[((size_t)bb * CCH + c) * NTOK + p];
    } else {
        v = in[(size_t)token * CCH + c];
    }
    float mu  = block_sum_256(v, sh) * (1.0f / 256.0f);
    float d   = v - mu;
    float var = block_sum_256(d * d, sh) * (1.0f / 256.0f);
    float r = d * rsqrtf(var + 1e-5f) * w[c] + bsh[c];
    if (BF16OUT) {
        __shared__ float row[CCH];
        row[c] = r;
        __syncthreads();
        if (c < CCH / 2)
            ((uint32_t*)outv)[(size_t)token * (CCH / 2) + c] =
                bf16pk(row[2 * c], row[2 * c + 1]);
    } else {
        ((float*)outv)[(size_t)token * CCH + c] = r;
    }
}

// ---------------- tf32 GEMM: k-slot remap, LDS.64 A-frags ----------------
// As stride 40 words, Bk stride 132 words. EPI0: plain. EPI1: bias+residual(x bchw).
template<int EPI>
__global__ void __launch_bounds__(256, 2) gemm_t_k(
    const float* __restrict__ A, const float* __restrict__ Bm,
    const float* __restrict__ bias, float* __restrict__ C,
    int M, int N, int K,
    const float* __restrict__ aux)
{
    __shared__ uint32_t As[2 * 128 * 40];
    __shared__ uint32_t Bk[2 * 32 * 132];

    const int tid  = threadIdx.x;
    const int w    = tid >> 5;
    const int lane = tid & 31;
    const int g    = lane >> 2;
    const int t    = lane & 3;
    const int wm   = w >> 1;
    const int wn   = w & 1;
    const int row0 = blockIdx.y * 128;
    const int col0 = blockIdx.x * 128;

    const uint32_t asb = (uint32_t)__cvta_generic_to_shared(As);
    const uint32_t bsb = (uint32_t)__cvta_generic_to_shared(Bk);

    float acc[2][8][4] = {};

    auto loadT = [&](int k0, int s) {
        #pragma unroll
        for (int p = 0; p < 4; p++) {
            int idx = p * 256 + tid;
            int m = idx >> 3, kq = (idx & 7) * 4;
            cpa16(asb + (uint32_t)(s * 5120 + m * 40 + kq) * 4,
                  A + (size_t)(row0 + m) * K + k0 + kq);
        }
        #pragma unroll
        for (int p = 0; p < 4; p++) {
            int idx = p * 256 + tid;
            int kk = idx >> 5, nq = (idx & 31) * 4;
            cpa16(bsb + (uint32_t)(s * 4224 + kk * 132 + nq) * 4,
                  Bm + (size_t)(k0 + kk) * N + col0 + nq);
        }
    };

    const int nk = K / 32;
    loadT(0, 0); CPC();

    for (int kt = 0; kt < nk; kt++) {
        int s = kt & 1;
        if (kt + 1 < nk) loadT((kt + 1) * 32, s ^ 1);
        CPC(); CPW1();
        __syncthreads();
        const uint32_t* as = As + s * 5120;
        const uint32_t* bs = Bk + s * 4224;
        #pragma unroll
        for (int k8 = 0; k8 < 4; k8++) {
            int kb = k8 * 8;
            // k-slot remap: slot t -> kb+2t, slot t+4 -> kb+2t+1
            uint2 a0[2], a1[2];
            #pragma unroll
            for (int mf = 0; mf < 2; mf++) {
                int mr = wm * 32 + mf * 16 + g;
                a0[mf] = *(const uint2*)&as[mr * 40 + kb + 2 * t];
                a1[mf] = *(const uint2*)&as[(mr + 8) * 40 + kb + 2 * t];
            }
            #pragma unroll
            for (int nf = 0; nf < 8; nf++) {
                int nc = wn * 64 + nf * 8 + g;
                uint32_t b0 = bs[(kb + 2 * t) * 132 + nc];
                uint32_t b1 = bs[(kb + 2 * t + 1) * 132 + nc];
                mma8(acc[0][nf], a0[0].x, a1[0].x, a0[0].y, a1[0].y, b0, b1);
                mma8(acc[1][nf], a0[1].x, a1[1].x, a0[1].y, a1[1].y, b0, b1);
            }
        }
        __syncthreads();
    }

    #pragma unroll
    for (int mf = 0; mf < 2; mf++) {
        #pragma unroll
        for (int nf = 0; nf < 8; nf++) {
            #pragma unroll
            for (int e = 0; e < 4; e++) {
                int m = row0 + wm * 32 + mf * 16 + g + ((e >> 1) ? 8 : 0);
                int n = col0 + wn * 64 + nf * 8 + 2 * t + (e & 1);
                float v = acc[mf][nf][e];
                if (EPI == 0) {
                    C[(size_t)m * N + n] = v;
                } else {
                    int bb2 = m >> 10, p = m & 1023;
                    v += bias[n] + aux[((size_t)bb2 * CCH + n) * NTOK + p];
                    C[(size_t)m * N + n] = v;
                }
            }
        }
    }
}

// ---------------- bf16 GEMM m16n8k16 (FFN path) ----------------
// A: bf16 [m][k] (stride 40 halves), B: k-paired bf16x2 [k/2][n] (stride 136).
// EPI 0: gelu(acc+bias) -> bf16x2 out. EPI 1: acc+bias+x3 -> transposed fp32 out.
template<int EPI>
__global__ void __launch_bounds__(256, 2) gemm_b_k(
    const uint32_t* __restrict__ Ab, const uint32_t* __restrict__ Bp,
    const float* __restrict__ bias, void* __restrict__ Cv,
    int M, int N, int K,
    const float* __restrict__ aux)
{
    __shared__ uint32_t As[2 * 128 * 20];   // 20 words = 40 bf16 per row
    __shared__ uint32_t Bs[2 * 16 * 136];

    const int tid  = threadIdx.x;
    const int w    = tid >> 5;
    const int lane = tid & 31;
    const int g    = lane >> 2;
    const int t    = lane & 3;
    const int wm   = w >> 1;
    const int wn   = w & 1;
    const int row0 = blockIdx.y * 128;
    const int col0 = blockIdx.x * 128;
    const int K2   = K / 2;

    const uint32_t asb = (uint32_t)__cvta_generic_to_shared(As);
    const uint32_t bsb = (uint32_t)__cvta_generic_to_shared(Bs);

    float acc[2][8][4] = {};

    auto loadT = [&](int k0, int s) {       // k0 in elements (mult of 32)
        #pragma unroll
        for (int p = 0; p < 2; p++) {
            int idx = p * 256 + tid;
            int m = idx >> 2, kq = (idx & 3) * 4;   // kq in words (4 words=8 bf16)
            cpa16(asb + (uint32_t)(s * 2560 + m * 20 + kq) * 4,
                  Ab + (size_t)(row0 + m) * K2 + k0 / 2 + kq);
        }
        #pragma unroll
        for (int p = 0; p < 2; p++) {
            int idx = p * 256 + tid;
            int kk = idx >> 5, nq = (idx & 31) * 4;
            cpa16(bsb + (uint32_t)(s * 2176 + kk * 136 + nq) * 4,
                  Bp + (size_t)(k0 / 2 + kk) * N + col0 + nq);
        }
    };

    const int nk = K / 32;
    loadT(0, 0); CPC();

    for (int kt = 0; kt < nk; kt++) {
        int s = kt & 1;
        if (kt + 1 < nk) loadT((kt + 1) * 32, s ^ 1);
        CPC(); CPW1();
        __syncthreads();
        const uint32_t* as = As + s * 2560;
        const uint32_t* bs = Bs + s * 2176;
        #pragma unroll
        for (int j = 0; j < 2; j++) {       // two k16 steps
            int kw = j * 8;                 // word offset within 20-word row
            uint32_t a[2][4];
            #pragma unroll
            for (int mf = 0; mf < 2; mf++) {
                int mr = wm * 32 + mf * 16 + g;
                a[mf][0] = as[mr * 20 + kw + t];
                a[mf][1] = as[(mr + 8) * 20 + kw + t];
                a[mf][2] = as[mr * 20 + kw + t + 4];
                a[mf][3] = as[(mr + 8) * 20 + kw + t + 4];
            }
            #pragma unroll
            for (int nf = 0; nf < 8; nf++) {
                int nc = wn * 64 + nf * 8 + g;
                uint32_t b0 = bs[(j * 8 + t) * 136 + nc];
                uint32_t b1 = bs[(j * 8 + t + 4) * 136 + nc];
                mma16b(acc[0][nf], a[0][0], a[0][1], a[0][2], a[0][3], b0, b1);
                mma16b(acc[1][nf], a[1][0], a[1][1], a[1][2], a[1][3], b0, b1);
            }
        }
        __syncthreads();
    }

    #pragma unroll
    for (int mf = 0; mf < 2; mf++) {
        #pragma unroll
        for (int nf = 0; nf < 8; nf++) {
            int n2 = col0 + wn * 64 + nf * 8 + 2 * t;
            #pragma unroll
            for (int half = 0; half < 2; half++) {
                int m = row0 + wm * 32 + mf * 16 + g + (half ? 8 : 0);
                float v0 = acc[mf][nf][2 * half];
                float v1 = acc[mf][nf][2 * half + 1];
                if (EPI == 0) {
                    v0 += bias[n2];
                    v1 += bias[n2 + 1];
                    v0 = 0.5f * v0 * (1.0f + erff(v0 * 0.7071067811865475f));
                    v1 = 0.5f * v1 * (1.0f + erff(v1 * 0.7071067811865475f));
                    ((uint32_t*)Cv)[(size_t)m * (N / 2) + n2 / 2] = bf16pk(v0, v1);
                } else {
                    int bb2 = m >> 10, p = m & 1023;
                    v0 += bias[n2]     + aux[(size_t)m * CCH + n2];
                    v1 += bias[n2 + 1] + aux[(size_t)m * CCH + n2 + 1];
                    float* o = (float*)Cv;
                    o[((size_t)bb2 * CCH + n2)     * NTOK + p] = v0;
                    o[((size_t)bb2 * CCH + n2 + 1) * NTOK + p] = v1;
                }
            }
        }
    }
}

// ---------------- tf32 MMA flash attention (R6 + LDS.64 K-frags) ----------
__global__ void __launch_bounds__(256, 2) attn_k(
    const float* __restrict__ qkv, const float* __restrict__ biasF,
    float* __restrict__ out)
{
    __shared__ uint32_t Ks[3][64 * 40];
    __shared__ uint32_t Vs[3][64 * 40];

    const int q0 = blockIdx.x * 128;
    const int h  = blockIdx.y;
    const int b  = blockIdx.z;
    const int tid = threadIdx.x;
    const int w = tid >> 5, lane = tid & 31;
    const int g = lane >> 2, t = lane & 3;

    const uint32_t ksb = (uint32_t)__cvta_generic_to_shared(Ks);
    const uint32_t vsb = (uint32_t)__cvta_generic_to_shared(Vs);

    auto ldkv = [&](int kt, int s) {
        #pragma unroll
        for (int p = 0; p < 2; p++) {
            int idx = p * 256 + tid;
            int m = idx >> 3, kq = (idx & 7) * 4;
            const float* kp = qkv + (size_t)(b * NTOK + kt * 64 + m) * 768
                              + 256 + h * 32 + kq;
            cpa16(ksb + (uint32_t)(s * 2560 + m * 40 + kq) * 4, kp);
            int vslot = (m & ~7) | ((m & 7) >> 1) | ((m & 1) << 2);
            cpa16(vsb + (uint32_t)(s * 2560 + vslot * 40 + kq) * 4, kp + 256);
        }
    };

    ldkv(0, 0); CPC();
    ldkv(1, 1); CPC();

    // Q fragments (k-slot remap: slot t -> kb+2t, slot t+4 -> kb+2t+1)
    uint32_t qf[4][4];
    {
        const float* qp = qkv + (size_t)(b * NTOK + q0 + w * 16) * 768 + h * 32;
        #pragma unroll
        for (int k8 = 0; k8 < 4; k8++) {
            int kb = k8 * 8;
            qf[k8][0] = __float_as_uint(qp[(size_t)g * 768 + kb + 2 * t]);
            qf[k8][1] = __float_as_uint(qp[(size_t)(g + 8) * 768 + kb + 2 * t]);
            qf[k8][2] = __float_as_uint(qp[(size_t)g * 768 + kb + 2 * t + 1]);
            qf[k8][3] = __float_as_uint(qp[(size_t)(g + 8) * 768 + kb + 2 * t + 1]);
        }
    }

    float o[4][4] = {};
    float l0 = 0.0f, l1 = 0.0f;
    const float scale = 0.17677669529663687f;
    const float* bbase = biasF + ((size_t)h << 20)
                         + (size_t)(q0 + w * 16 + g) * NTOK + 2 * t;

    for (int kt = 0; kt < 16; kt++) {
        int s = kt % 3;
        if (kt < 15) { CPW1(); } else { CPW0(); }
        __syncthreads();
        if (kt + 2 < 16) { ldkv(kt + 2, (kt + 2) % 3); CPC(); }
        const uint32_t* ks = Ks[s];
        const uint32_t* vs = Vs[s];

        // ---- QK: LDS.64 K frags via remapped slots ----
        float c[8][4] = {};
        #pragma unroll
        for (int k8 = 0; k8 < 4; k8++) {
            int kb = k8 * 8;
            #pragma unroll
            for (int nf = 0; nf < 8; nf++) {
                int kc = nf * 8 + g;
                uint2 bb2 = *(const uint2*)&ks[kc * 40 + kb + 2 * t];
                mma8(c[nf], qf[k8][0], qf[k8][1], qf[k8][2], qf[k8][3],
                     bb2.x, bb2.y);
            }
        }

        // ---- softmax piece ----
        const float* bp = bbase + kt * 64;
        #pragma unroll
        for (int nf = 0; nf < 8; nf++) {
            float2 bA = *(const float2*)(bp + nf * 8);
            float2 bB = *(const float2*)(bp + 8 * NTOK + nf * 8);
            c[nf][0] = tf32trunc(__expf(fmaf(c[nf][0], scale, bA.x)));
            c[nf][1] = tf32trunc(__expf(fmaf(c[nf][1], scale, bA.y)));
            c[nf][2] = tf32trunc(__expf(fmaf(c[nf][2], scale, bB.x)));
            c[nf][3] = tf32trunc(__expf(fmaf(c[nf][3], scale, bB.y)));
            l0 += c[nf][0] + c[nf][1];
            l1 += c[nf][2] + c[nf][3];
        }

        // ---- PV: P from registers, V rows pre-permuted ----
        #pragma unroll
        for (int j = 0; j < 8; j++) {
            uint32_t a0 = __float_as_uint(c[j][0]);
            uint32_t a1 = __float_as_uint(c[j][2]);
            uint32_t a2 = __float_as_uint(c[j][1]);
            uint32_t a3 = __float_as_uint(c[j][3]);
            #pragma unroll
            for (int dn = 0; dn < 4; dn++) {
                mma8(o[dn], a0, a1, a2, a3,
                     vs[(j * 8 + t) * 40 + dn * 8 + g],
                     vs[(j * 8 + t + 4) * 40 + dn * 8 + g]);
            }
        }
    }

    // deferred denominator reduction (once, not per tile)
    l0 += __shfl_xor_sync(0xffffffffu, l0, 1);
    l0 += __shfl_xor_sync(0xffffffffu, l0, 2);
    l1 += __shfl_xor_sync(0xffffffffu, l1, 1);
    l1 += __shfl_xor_sync(0xffffffffu, l1, 2);

    float inv0 = 1.0f / l0, inv1 = 1.0f / l1;
    float* op = out + (size_t)(b * NTOK + q0 + w * 16 + g) * CCH + h * 32;
    #pragma unroll
    for (int dn = 0; dn < 4; dn++) {
        *(float2*)(op + dn * 8 + 2 * t) =
            make_float2(o[dn][0] * inv0, o[dn][1] * inv0);
        *(float2*)(op + 8 * CCH + dn * 8 + 2 * t) =
            make_float2(o[dn][2] * inv1, o[dn][3] * inv1);
    }
}

// ---------------- launch ----------------
extern "C" void kernel_launch(void* const* d_in, const int* in_sizes, int n_in,
                              void* d_out, int out_size)
{
    const float* x       = (const float*)d_in[0];
    const float* qkv_w   = (const float*)d_in[1];
    const float* proj_w  = (const float*)d_in[2];
    const float* proj_b  = (const float*)d_in[3];
    const float* ffn_w1  = (const float*)d_in[4];
    const float* ffn_b1  = (const float*)d_in[5];
    const float* ffn_w2  = (const float*)d_in[6];
    const float* ffn_b2  = (const float*)d_in[7];
    const float* n1w     = (const float*)d_in[8];
    const float* n1b     = (const float*)d_in[9];
    const float* n2w     = (const float*)d_in[10];
    const float* n2b     = (const float*)d_in[11];
    const float* table   = (const float*)d_in[12];
    const int*   relidx  = (const int*)d_in[13];
    float* out = (float*)d_out;

    void *px1, *pqkv, *pbias, *pattn, *px3, *px4b, *pffnb, *pw1p, *pw2p;
    cudaGetSymbolAddress(&px1,   g_x1);
    cudaGetSymbolAddress(&pqkv,  g_qkv);
    cudaGetSymbolAddress(&pbias, g_bias);
    cudaGetSymbolAddress(&pattn, g_attn);
    cudaGetSymbolAddress(&px3,   g_x3);
    cudaGetSymbolAddress(&px4b,  g_x4b);
    cudaGetSymbolAddress(&pffnb, g_ffnb);
    cudaGetSymbolAddress(&pw1p,  g_w1p);
    cudaGetSymbolAddress(&pw2p,  g_w2p);

    // weight converts (small)
    wcvt_k<<<(CCH / 2 * HID + 255) / 256, 256>>>(ffn_w1, (uint32_t*)pw1p,
                                                 CCH / 2, HID);
    wcvt_k<<<(HID / 2 * CCH + 255) / 256, 256>>>(ffn_w2, (uint32_t*)pw2p,
                                                 HID / 2, CCH);
    expand_bias_k<<<NN / 256, 256>>>(table, relidx, (float*)pbias);
    ln_k<1, 0><<<MTOT, 256>>>(x, n1w, n1b, px1);
    gemm_t_k<0><<<dim3(768 / 128, MTOT / 128), 256>>>(
        (const float*)px1, qkv_w, nullptr, (float*)pqkv,
        MTOT, 768, 256, nullptr);
    attn_k<<<dim3(NTOK / 128, NHEAD, BATCH), 256>>>(
        (const float*)pqkv, (const float*)pbias, (float*)pattn);
    gemm_t_k<1><<<dim3(256 / 128, MTOT / 128), 256>>>(
        (const float*)pattn, proj_w, proj_b, (float*)px3,
        MTOT, 256, 256, x);
    ln_k<0, 1><<<MTOT, 256>>>((const float*)px3, n2w, n2b, px4b);
    gemm_b_k<0><<<dim3(HID / 128, MTOT / 128), 256>>>(
        (const uint32_t*)px4b, (const uint32_t*)pw1p, ffn_b1, pffnb,
        MTOT, HID, 256, nullptr);
    gemm_b_k<1><<<dim3(256 / 128, MTOT / 128), 256>>>(
        (const uint32_t*)pffnb, (const uint32_t*)pw2p, ffn_b2, out,
        MTOT, 256, 1024, (const float*)px3);
}

// round 8
// speedup vs baseline: 6.8383x; 1.1690x over previous
#include <cuda_runtime.h>
#include <cuda_bf16.h>
#include <math.h>
#include <stdint.h>

#define BATCH 16
#define CCH   256
#define NTOK  1024
#define NN    (1024*1024)
#define NHEAD 8
#define HID   1024
#define MTOT  (BATCH*NTOK)   // 16384

// ---------------- helpers ----------------
__device__ __forceinline__ void mma16b(float c[4], uint32_t a0, uint32_t a1,
                                       uint32_t a2, uint32_t a3,
                                       uint32_t b0, uint32_t b1) {
    asm("mma.sync.aligned.m16n8k16.row.col.f32.bf16.bf16.f32 "
        "{%0,%1,%2,%3}, {%4,%5,%6,%7}, {%8,%9}, {%0,%1,%2,%3};"
        : "+f"(c[0]), "+f"(c[1]), "+f"(c[2]), "+f"(c[3])
        : "r"(a0), "r"(a1), "r"(a2), "r"(a3), "r"(b0), "r"(b1));
}
__device__ __forceinline__ uint32_t bf16pk(float lo, float hi) {
    uint32_t r;
    asm("cvt.rn.bf16x2.f32 %0, %1, %2;" : "=r"(r) : "f"(hi), "f"(lo));
    return r;
}
__device__ __forceinline__ void cpa16(uint32_t dst, const void* src) {
    asm volatile("cp.async.cg.shared.global [%0], [%1], 16;"
                 :: "r"(dst), "l"(src) : "memory");
}
#define CPC()  asm volatile("cp.async.commit_group;" ::: "memory")
#define CPW1() asm volatile("cp.async.wait_group 1;" ::: "memory")
#define CPW0() asm volatile("cp.async.wait_group 0;" ::: "memory")

// ---------------- scratch ----------------
__device__ uint32_t g_x1b [MTOT*128];        // LN1 out bf16x2 [token][128w]
__device__ uint32_t g_qb  [MTOT*128];        // Q bf16x2 (pairs along d)
__device__ uint32_t g_kb  [MTOT*128];        // K bf16x2 (pairs along d)
__device__ float    g_vf  [MTOT*CCH];        // V fp32 [token][256]
__device__ uint32_t g_vt  [BATCH*NHEAD*32*512]; // V bf16x2 [b,h,d][tokpair]
__device__ uint32_t g_ob  [MTOT*128];        // attn out bf16x2
__device__ float    g_bias[NHEAD*NN];
__device__ float    g_x3  [MTOT*CCH];
__device__ uint32_t g_x4b [MTOT*128];        // LN2 out bf16x2
__device__ uint32_t g_ffnb[MTOT*512];        // gelu out bf16x2
__device__ uint32_t g_wqkv[128*768];
__device__ uint32_t g_wprj[128*256];
__device__ uint32_t g_w1p [128*HID];
__device__ uint32_t g_w2p [512*256];

// ---------------- weight convert: fp32 [K][N] -> k-paired bf16x2 [K/2][N] ---
__global__ void __launch_bounds__(256) wcvt_k(
    const float* __restrict__ w, uint32_t* __restrict__ wp, int K2, int N)
{
    int i = blockIdx.x * 256 + threadIdx.x;
    if (i >= K2 * N) return;
    int k2 = i / N, n = i - k2 * N;
    wp[i] = bf16pk(w[(size_t)(2 * k2) * N + n], w[(size_t)(2 * k2 + 1) * N + n]);
}

// ---------------- bias expand ----------------
__global__ void __launch_bounds__(256) expand_bias_k(
    const float* __restrict__ table, const int* __restrict__ relidx,
    float* __restrict__ biasF)
{
    int t = blockIdx.x * 256 + threadIdx.x;
    int idx = relidx[t];
    #pragma unroll
    for (int h = 0; h < NHEAD; h++)
        biasF[(size_t)h * NN + t] = table[idx * NHEAD + h];
}

// ---------------- LN1: coalesced bchw read via smem transpose, bf16 out ----
__global__ void __launch_bounds__(256) ln1t_k(
    const float* __restrict__ x, const float* __restrict__ w,
    const float* __restrict__ bsh, uint32_t* __restrict__ outb)
{
    __shared__ float sm[256][33];
    __shared__ float red[8][32];
    __shared__ float musm[32], rssm[32];
    const int bb = blockIdx.y, p0 = blockIdx.x * 32;
    const int tid = threadIdx.x;

    #pragma unroll
    for (int pass = 0; pass < 8; pass++) {
        int idx = pass * 256 + tid;
        int c = idx >> 3, f = (idx & 7) * 4;
        float4 v = *(const float4*)&x[((size_t)(bb * 256 + c) << 10) + p0 + f];
        sm[c][f] = v.x; sm[c][f + 1] = v.y; sm[c][f + 2] = v.z; sm[c][f + 3] = v.w;
    }
    __syncthreads();
    const int p = tid & 31, sub = tid >> 5;
    float s = 0.0f;
    #pragma unroll
    for (int i = 0; i < 32; i++) s += sm[sub * 32 + i][p];
    red[sub][p] = s;
    __syncthreads();
    if (sub == 0) {
        float m = 0.0f;
        #pragma unroll
        for (int i = 0; i < 8; i++) m += red[i][p];
        musm[p] = m * (1.0f / 256.0f);
    }
    __syncthreads();
    float mu = musm[p], vs = 0.0f;
    #pragma unroll
    for (int i = 0; i < 32; i++) {
        float d = sm[sub * 32 + i][p] - mu;
        vs += d * d;
    }
    red[sub][p] = vs;
    __syncthreads();
    if (sub == 0) {
        float m = 0.0f;
        #pragma unroll
        for (int i = 0; i < 8; i++) m += red[i][p];
        rssm[p] = rsqrtf(m * (1.0f / 256.0f) + 1e-5f);
    }
    __syncthreads();
    const int tk = tid >> 3, ch = (tid & 7) * 32;
    const float mu2 = musm[tk], rs = rssm[tk];
    #pragma unroll
    for (int i = 0; i < 8; i++) {
        int c = ch + i * 4;
        float o0 = (sm[c][tk]     - mu2) * rs * w[c]     + bsh[c];
        float o1 = (sm[c + 1][tk] - mu2) * rs * w[c + 1] + bsh[c + 1];
        float o2 = (sm[c + 2][tk] - mu2) * rs * w[c + 2] + bsh[c + 2];
        float o3 = (sm[c + 3][tk] - mu2) * rs * w[c + 3] + bsh[c + 3];
        *(uint2*)&outb[(size_t)(bb * 1024 + p0 + tk) * 128 + c / 2] =
            make_uint2(bf16pk(o0, o1), bf16pk(o2, o3));
    }
}

// ---------------- LN2: row-major in, bf16 out ----------------
__device__ __forceinline__ float block_sum_256(float v, float* sh)
{
    __syncthreads();
    int lane = threadIdx.x & 31, wid = threadIdx.x >> 5;
    #pragma unroll
    for (int o = 16; o; o >>= 1) v += __shfl_xor_sync(0xffffffffu, v, o);
    if (!lane) sh[wid] = v;
    __syncthreads();
    if (threadIdx.x < 8) {
        float t = sh[threadIdx.x];
        #pragma unroll
        for (int o = 4; o; o >>= 1) t += __shfl_xor_sync(0xffu, t, o);
        if (!threadIdx.x) sh[0] = t;
    }
    __syncthreads();
    return sh[0];
}

__global__ void __launch_bounds__(256) ln2_k(
    const float* __restrict__ in, const float* __restrict__ w,
    const float* __restrict__ bsh, uint32_t* __restrict__ outb)
{
    __shared__ float sh[8];
    __shared__ float row[CCH];
    int token = blockIdx.x;
    int c = threadIdx.x;
    float v = in[(size_t)token * CCH + c];
    float mu  = block_sum_256(v, sh) * (1.0f / 256.0f);
    float d   = v - mu;
    float var = block_sum_256(d * d, sh) * (1.0f / 256.0f);
    row[c] = d * rsqrtf(var + 1e-5f) * w[c] + bsh[c];
    __syncthreads();
    if (c < CCH / 2)
        outb[(size_t)token * 128 + c] = bf16pk(row[2 * c], row[2 * c + 1]);
}

// ---------------- V transpose-pack: fp32 [tok][256] -> bf16x2 [b,h,d][tp] ---
__global__ void __launch_bounds__(256) vt_cvt_k(
    const float* __restrict__ vf, uint32_t* __restrict__ vt)
{
    __shared__ float sm[128][33];
    const int tile = blockIdx.x, h = blockIdx.y, b = blockIdx.z;
    const int t0 = tile * 128;
    const int tid = threadIdx.x;
    #pragma unroll
    for (int pass = 0; pass < 4; pass++) {
        int idx = pass * 256 + tid;
        int tok = idx >> 3, f = (idx & 7) * 4;
        float4 v = *(const float4*)&vf[(size_t)(b * 1024 + t0 + tok) * 256
                                       + h * 32 + f];
        sm[tok][f] = v.x; sm[tok][f + 1] = v.y;
        sm[tok][f + 2] = v.z; sm[tok][f + 3] = v.w;
    }
    __syncthreads();
    const int d = tid >> 3, jb = (tid & 7) * 8;
    uint32_t wbuf[8];
    #pragma unroll
    for (int i = 0; i < 8; i++) {
        int j = jb + i;
        wbuf[i] = bf16pk(sm[2 * j][d], sm[2 * j + 1][d]);
    }
    uint32_t* dst = vt + ((size_t)(b * NHEAD + h) * 32 + d) * 512 + tile * 64 + jb;
    *(uint4*)dst       = make_uint4(wbuf[0], wbuf[1], wbuf[2], wbuf[3]);
    *(uint4*)(dst + 4) = make_uint4(wbuf[4], wbuf[5], wbuf[6], wbuf[7]);
}

// ---------------- unified bf16 GEMM m16n8k16, cp.async 2-stage ----------------
// A: bf16x2 [m][K/2 words], B: k-paired bf16x2 [K/2][N].
// EPI 0: gelu(acc+bias) -> bf16x2.  EPI 1: acc+bias+x3 -> bchw fp32 (final).
// EPI 2: qkv split -> Qb/Kb bf16x2, Vf fp32.  EPI 3: acc+bias+x(bchw) -> fp32.
template<int EPI>
__global__ void __launch_bounds__(256, 2) gemm_b_k(
    const uint32_t* __restrict__ Ab, const uint32_t* __restrict__ Bp,
    const float* __restrict__ bias, void* __restrict__ Cv,
    int M, int N, int K,
    const float* __restrict__ aux,
    uint32_t* __restrict__ qb, uint32_t* __restrict__ kb,
    float* __restrict__ vf)
{
    __shared__ uint32_t As[2 * 128 * 20];
    __shared__ uint32_t Bs[2 * 16 * 136];

    const int tid  = threadIdx.x;
    const int w    = tid >> 5;
    const int lane = tid & 31;
    const int g    = lane >> 2;
    const int t    = lane & 3;
    const int wm   = w >> 1;
    const int wn   = w & 1;
    const int row0 = blockIdx.y * 128;
    const int col0 = blockIdx.x * 128;
    const int K2   = K / 2;

    const uint32_t asb = (uint32_t)__cvta_generic_to_shared(As);
    const uint32_t bsb = (uint32_t)__cvta_generic_to_shared(Bs);

    float acc[2][8][4] = {};

    auto loadT = [&](int k0, int s) {
        #pragma unroll
        for (int p = 0; p < 2; p++) {
            int idx = p * 256 + tid;
            int m = idx >> 2, kq = (idx & 3) * 4;
            cpa16(asb + (uint32_t)(s * 2560 + m * 20 + kq) * 4,
                  Ab + (size_t)(row0 + m) * K2 + k0 / 2 + kq);
        }
        #pragma unroll
        for (int p = 0; p < 2; p++) {
            int idx = p * 256 + tid;
            int kk = idx >> 5, nq = (idx & 31) * 4;
            cpa16(bsb + (uint32_t)(s * 2176 + kk * 136 + nq) * 4,
                  Bp + (size_t)(k0 / 2 + kk) * N + col0 + nq);
        }
    };

    const int nk = K / 32;
    loadT(0, 0); CPC();

    for (int kt = 0; kt < nk; kt++) {
        int s = kt & 1;
        if (kt + 1 < nk) loadT((kt + 1) * 32, s ^ 1);
        CPC(); CPW1();
        __syncthreads();
        const uint32_t* as = As + s * 2560;
        const uint32_t* bs = Bs + s * 2176;
        #pragma unroll
        for (int j = 0; j < 2; j++) {
            int kw = j * 8;
            uint32_t a[2][4];
            #pragma unroll
            for (int mf = 0; mf < 2; mf++) {
                int mr = wm * 32 + mf * 16 + g;
                a[mf][0] = as[mr * 20 + kw + t];
                a[mf][1] = as[(mr + 8) * 20 + kw + t];
                a[mf][2] = as[mr * 20 + kw + t + 4];
                a[mf][3] = as[(mr + 8) * 20 + kw + t + 4];
            }
            #pragma unroll
            for (int nf = 0; nf < 8; nf++) {
                int nc = wn * 64 + nf * 8 + g;
                uint32_t b0 = bs[(j * 8 + t) * 136 + nc];
                uint32_t b1 = bs[(j * 8 + t + 4) * 136 + nc];
                mma16b(acc[0][nf], a[0][0], a[0][1], a[0][2], a[0][3], b0, b1);
                mma16b(acc[1][nf], a[1][0], a[1][1], a[1][2], a[1][3], b0, b1);
            }
        }
        __syncthreads();
    }

    #pragma unroll
    for (int mf = 0; mf < 2; mf++) {
        #pragma unroll
        for (int nf = 0; nf < 8; nf++) {
            int n2 = col0 + wn * 64 + nf * 8 + 2 * t;
            #pragma unroll
            for (int half = 0; half < 2; half++) {
                int m = row0 + wm * 32 + mf * 16 + g + (half ? 8 : 0);
                float v0 = acc[mf][nf][2 * half];
                float v1 = acc[mf][nf][2 * half + 1];
                if (EPI == 0) {
                    v0 += bias[n2];
                    v1 += bias[n2 + 1];
                    v0 = 0.5f * v0 * (1.0f + erff(v0 * 0.7071067811865475f));
                    v1 = 0.5f * v1 * (1.0f + erff(v1 * 0.7071067811865475f));
                    ((uint32_t*)Cv)[(size_t)m * (N / 2) + n2 / 2] = bf16pk(v0, v1);
                } else if (EPI == 1) {
                    int bb2 = m >> 10, p = m & 1023;
                    v0 += bias[n2]     + aux[(size_t)m * CCH + n2];
                    v1 += bias[n2 + 1] + aux[(size_t)m * CCH + n2 + 1];
                    float* o = (float*)Cv;
                    o[((size_t)bb2 * CCH + n2)     * NTOK + p] = v0;
                    o[((size_t)bb2 * CCH + n2 + 1) * NTOK + p] = v1;
                } else if (EPI == 2) {
                    if (n2 < 256) {
                        qb[(size_t)m * 128 + n2 / 2] = bf16pk(v0, v1);
                    } else if (n2 < 512) {
                        kb[(size_t)m * 128 + (n2 - 256) / 2] = bf16pk(v0, v1);
                    } else {
                        vf[(size_t)m * 256 + (n2 - 512)]     = v0;
                        vf[(size_t)m * 256 + (n2 - 512) + 1] = v1;
                    }
                } else {
                    int bb2 = m >> 10, p = m & 1023;
                    v0 += bias[n2]     + aux[(((size_t)bb2 * CCH + n2) << 10) + p];
                    v1 += bias[n2 + 1] + aux[(((size_t)bb2 * CCH + n2 + 1) << 10) + p];
                    float* o = (float*)Cv;
                    o[(size_t)m * CCH + n2]     = v0;
                    o[(size_t)m * CCH + n2 + 1] = v1;
                }
            }
        }
    }
}

// ---------------- bf16 flash attention, P-in-register, 3-stage ring ----------
__global__ void __launch_bounds__(256, 2) attn_k(
    const uint32_t* __restrict__ Qb, const uint32_t* __restrict__ Kb,
    const uint32_t* __restrict__ Vt, const float* __restrict__ biasF,
    uint32_t* __restrict__ outb)
{
    __shared__ uint32_t Ks[3][64 * 20];
    __shared__ uint32_t Vs[3][32 * 36];

    const int q0 = blockIdx.x * 128;
    const int h  = blockIdx.y;
    const int b  = blockIdx.z;
    const int tid = threadIdx.x;
    const int wid = tid >> 5, lane = tid & 31;
    const int g = lane >> 2, t = lane & 3;

    const uint32_t ksb = (uint32_t)__cvta_generic_to_shared(Ks);
    const uint32_t vsb = (uint32_t)__cvta_generic_to_shared(Vs);

    auto ldkv = [&](int kt, int s) {
        {   // K: 64 rows x 16 words
            int m = tid >> 2, kqw = (tid & 3) * 4;
            cpa16(ksb + (uint32_t)(s * 1280 + m * 20 + kqw) * 4,
                  Kb + (size_t)(b * NTOK + kt * 64 + m) * 128 + h * 16 + kqw);
        }
        {   // V: 32 d-rows x 32 words
            int m = tid >> 3, q8 = (tid & 7) * 4;
            cpa16(vsb + (uint32_t)(s * 1152 + m * 36 + q8) * 4,
                  Vt + ((size_t)(b * NHEAD + h) * 32 + m) * 512 + kt * 32 + q8);
        }
    };

    ldkv(0, 0); CPC();
    ldkv(1, 1); CPC();

    // Q fragments hoisted (bf16x2 words, pairs along d)
    uint32_t qf[2][4];
    {
        const uint32_t* qp = Qb + (size_t)(b * NTOK + q0 + wid * 16) * 128 + h * 16;
        #pragma unroll
        for (int j = 0; j < 2; j++) {
            qf[j][0] = qp[(size_t)g * 128 + j * 8 + t];
            qf[j][1] = qp[(size_t)(g + 8) * 128 + j * 8 + t];
            qf[j][2] = qp[(size_t)g * 128 + j * 8 + 4 + t];
            qf[j][3] = qp[(size_t)(g + 8) * 128 + j * 8 + 4 + t];
        }
    }

    float o[4][4] = {};
    float l0 = 0.0f, l1 = 0.0f;
    const float scale = 0.17677669529663687f;
    const float* bbase = biasF + ((size_t)h << 20)
                         + (size_t)(q0 + wid * 16 + g) * NTOK + 2 * t;

    for (int kt = 0; kt < 16; kt++) {
        int s = kt % 3;
        if (kt < 15) { CPW1(); } else { CPW0(); }
        __syncthreads();
        if (kt + 2 < 16) { ldkv(kt + 2, (kt + 2) % 3); CPC(); }
        const uint32_t* ks = Ks[s];
        const uint32_t* vs = Vs[s];

        // ---- QK: 16q x 64k per warp, bf16 k16 ----
        float c[8][4] = {};
        #pragma unroll
        for (int j = 0; j < 2; j++) {
            #pragma unroll
            for (int nf = 0; nf < 8; nf++) {
                int kc = nf * 8 + g;
                mma16b(c[nf], qf[j][0], qf[j][1], qf[j][2], qf[j][3],
                       ks[kc * 20 + j * 8 + t], ks[kc * 20 + j * 8 + 4 + t]);
            }
        }

        // ---- softmax piece ----
        const float* bp = bbase + kt * 64;
        #pragma unroll
        for (int nf = 0; nf < 8; nf++) {
            float2 bA = *(const float2*)(bp + nf * 8);
            float2 bB = *(const float2*)(bp + 8 * NTOK + nf * 8);
            c[nf][0] = __expf(fmaf(c[nf][0], scale, bA.x));
            c[nf][1] = __expf(fmaf(c[nf][1], scale, bA.y));
            c[nf][2] = __expf(fmaf(c[nf][2], scale, bB.x));
            c[nf][3] = __expf(fmaf(c[nf][3], scale, bB.y));
            l0 += c[nf][0] + c[nf][1];
            l1 += c[nf][2] + c[nf][3];
        }

        // ---- PV: P packed from registers, bf16 k16 ----
        #pragma unroll
        for (int j = 0; j < 4; j++) {
            uint32_t a0 = bf16pk(c[2 * j][0], c[2 * j][1]);
            uint32_t a1 = bf16pk(c[2 * j][2], c[2 * j][3]);
            uint32_t a2 = bf16pk(c[2 * j + 1][0], c[2 * j + 1][1]);
            uint32_t a3 = bf16pk(c[2 * j + 1][2], c[2 * j + 1][3]);
            #pragma unroll
            for (int dn = 0; dn < 4; dn++) {
                int vcb = (dn * 8 + g) * 36 + j * 8;
                mma16b(o[dn], a0, a1, a2, a3, vs[vcb + t], vs[vcb + 4 + t]);
            }
        }
    }

    l0 += __shfl_xor_sync(0xffffffffu, l0, 1);
    l0 += __shfl_xor_sync(0xffffffffu, l0, 2);
    l1 += __shfl_xor_sync(0xffffffffu, l1, 1);
    l1 += __shfl_xor_sync(0xffffffffu, l1, 2);

    float inv0 = 1.0f / l0, inv1 = 1.0f / l1;
    uint32_t* op = outb + (size_t)(b * NTOK + q0 + wid * 16 + g) * 128 + h * 16;
    #pragma unroll
    for (int dn = 0; dn < 4; dn++) {
        op[dn * 4 + t]            = bf16pk(o[dn][0] * inv0, o[dn][1] * inv0);
        op[8 * 128 + dn * 4 + t]  = bf16pk(o[dn][2] * inv1, o[dn][3] * inv1);
    }
}

// ---------------- launch ----------------
extern "C" void kernel_launch(void* const* d_in, const int* in_sizes, int n_in,
                              void* d_out, int out_size)
{
    const float* x       = (const float*)d_in[0];
    const float* qkv_w   = (const float*)d_in[1];
    const float* proj_w  = (const float*)d_in[2];
    const float* proj_b  = (const float*)d_in[3];
    const float* ffn_w1  = (const float*)d_in[4];
    const float* ffn_b1  = (const float*)d_in[5];
    const float* ffn_w2  = (const float*)d_in[6];
    const float* ffn_b2  = (const float*)d_in[7];
    const float* n1w     = (const float*)d_in[8];
    const float* n1b     = (const float*)d_in[9];
    const float* n2w     = (const float*)d_in[10];
    const float* n2b     = (const float*)d_in[11];
    const float* table   = (const float*)d_in[12];
    const int*   relidx  = (const int*)d_in[13];
    float* out = (float*)d_out;

    void *px1b, *pqb, *pkb, *pvf, *pvt, *pob, *pbias, *px3, *px4b, *pffnb;
    void *pwqkv, *pwprj, *pw1p, *pw2p;
    cudaGetSymbolAddress(&px1b,  g_x1b);
    cudaGetSymbolAddress(&pqb,   g_qb);
    cudaGetSymbolAddress(&pkb,   g_kb);
    cudaGetSymbolAddress(&pvf,   g_vf);
    cudaGetSymbolAddress(&pvt,   g_vt);
    cudaGetSymbolAddress(&pob,   g_ob);
    cudaGetSymbolAddress(&pbias, g_bias);
    cudaGetSymbolAddress(&px3,   g_x3);
    cudaGetSymbolAddress(&px4b,  g_x4b);
    cudaGetSymbolAddress(&pffnb, g_ffnb);
    cudaGetSymbolAddress(&pwqkv, g_wqkv);
    cudaGetSymbolAddress(&pwprj, g_wprj);
    cudaGetSymbolAddress(&pw1p,  g_w1p);
    cudaGetSymbolAddress(&pw2p,  g_w2p);

    wcvt_k<<<(128 * 768 + 255) / 256, 256>>>(qkv_w, (uint32_t*)pwqkv, 128, 768);
    wcvt_k<<<(128 * 256 + 255) / 256, 256>>>(proj_w, (uint32_t*)pwprj, 128, 256);
    wcvt_k<<<(128 * HID + 255) / 256, 256>>>(ffn_w1, (uint32_t*)pw1p, 128, HID);
    wcvt_k<<<(512 * 256 + 255) / 256, 256>>>(ffn_w2, (uint32_t*)pw2p, 512, 256);
    expand_bias_k<<<NN / 256, 256>>>(table, relidx, (float*)pbias);

    ln1t_k<<<dim3(32, BATCH), 256>>>(x, n1w, n1b, (uint32_t*)px1b);
    gemm_b_k<2><<<dim3(6, 128), 256>>>(
        (const uint32_t*)px1b, (const uint32_t*)pwqkv, nullptr, nullptr,
        MTOT, 768, 256, nullptr,
        (uint32_t*)pqb, (uint32_t*)pkb, (float*)pvf);
    vt_cvt_k<<<dim3(8, NHEAD, BATCH), 256>>>((const float*)pvf, (uint32_t*)pvt);
    attn_k<<<dim3(NTOK / 128, NHEAD, BATCH), 256>>>(
        (const uint32_t*)pqb, (const uint32_t*)pkb, (const uint32_t*)pvt,
        (const float*)pbias, (uint32_t*)pob);
    gemm_b_k<3><<<dim3(2, 128), 256>>>(
        (const uint32_t*)pob, (const uint32_t*)pwprj, proj_b, px3,
        MTOT, 256, 256, x, nullptr, nullptr, nullptr);
    ln2_k<<<MTOT, 256>>>((const float*)px3, n2w, n2b, (uint32_t*)px4b);
    gemm_b_k<0><<<dim3(8, 128), 256>>>(
        (const uint32_t*)px4b, (const uint32_t*)pw1p, ffn_b1, pffnb,
        MTOT, HID, 256, nullptr, nullptr, nullptr, nullptr);
    gemm_b_k<1><<<dim3(2, 128), 256>>>(
        (const uint32_t*)pffnb, (const uint32_t*)pw2p, ffn_b2, out,
        MTOT, 256, 1024, (const float*)px3, nullptr, nullptr, nullptr);
}

// round 10
// speedup vs baseline: 7.8899x; 1.1538x over previous
#include <cuda_runtime.h>
#include <cuda_bf16.h>
#include <math.h>
#include <stdint.h>

#define BATCH 16
#define CCH   256
#define NTOK  1024
#define NN    (1024*1024)
#define NHEAD 8
#define HID   1024
#define MTOT  (BATCH*NTOK)   // 16384

// ---------------- helpers ----------------
__device__ __forceinline__ void mma16b(float c[4], uint32_t a0, uint32_t a1,
                                       uint32_t a2, uint32_t a3,
                                       uint32_t b0, uint32_t b1) {
    asm("mma.sync.aligned.m16n8k16.row.col.f32.bf16.bf16.f32 "
        "{%0,%1,%2,%3}, {%4,%5,%6,%7}, {%8,%9}, {%0,%1,%2,%3};"
        : "+f"(c[0]), "+f"(c[1]), "+f"(c[2]), "+f"(c[3])
        : "r"(a0), "r"(a1), "r"(a2), "r"(a3), "r"(b0), "r"(b1));
}
__device__ __forceinline__ uint32_t bf16pk(float lo, float hi) {
    uint32_t r;
    asm("cvt.rn.bf16x2.f32 %0, %1, %2;" : "=r"(r) : "f"(hi), "f"(lo));
    return r;
}
__device__ __forceinline__ float2 upbf(uint32_t u) {
    float2 r;
    r.x = __uint_as_float(u << 16);
    r.y = __uint_as_float(u & 0xffff0000u);
    return r;
}
__device__ __forceinline__ void cpa16(uint32_t dst, const void* src) {
    asm volatile("cp.async.cg.shared.global [%0], [%1], 16;"
                 :: "r"(dst), "l"(src) : "memory");
}
#define CPC()  asm volatile("cp.async.commit_group;" ::: "memory")
#define CPW1() asm volatile("cp.async.wait_group 1;" ::: "memory")
#define CPW0() asm volatile("cp.async.wait_group 0;" ::: "memory")

// ---------------- scratch ----------------
__device__ uint32_t g_x1b [MTOT*128];
__device__ uint32_t g_qb  [MTOT*128];
__device__ uint32_t g_kb  [MTOT*128];
__device__ float    g_vf  [MTOT*CCH];
__device__ uint32_t g_vt  [BATCH*NHEAD*32*512];
__device__ uint32_t g_ob  [MTOT*128];
__device__ uint32_t g_biasb[NHEAD*NN/2];     // bf16x2 bias [h][i][j-pair]
__device__ float    g_x3  [MTOT*CCH];
__device__ uint32_t g_x4b [MTOT*128];
__device__ uint32_t g_ffnb[MTOT*512];
__device__ uint32_t g_wqkv[128*768];
__device__ uint32_t g_wprj[128*256];
__device__ uint32_t g_w1p [128*HID];
__device__ uint32_t g_w2p [512*256];

// ---------------- fused weight convert (4 matrices, one kernel) -------------
__global__ void __launch_bounds__(256) wcvt4_k(
    const float* __restrict__ w0, const float* __restrict__ w1,
    const float* __restrict__ w2, const float* __restrict__ w3,
    uint32_t* __restrict__ o0, uint32_t* __restrict__ o1,
    uint32_t* __restrict__ o2, uint32_t* __restrict__ o3)
{
    int i = blockIdx.x * 256 + threadIdx.x;
    const float* w; uint32_t* o; int N, li;
    if (i < 98304)       { w = w0; o = o0; N = 768;  li = i; }
    else if (i < 131072) { w = w1; o = o1; N = 256;  li = i - 98304; }
    else if (i < 262144) { w = w2; o = o2; N = 1024; li = i - 131072; }
    else                 { w = w3; o = o3; N = 256;  li = i - 262144; }
    int k2 = li / N, n = li - k2 * N;
    o[li] = bf16pk(w[(size_t)(2 * k2) * N + n], w[(size_t)(2 * k2 + 1) * N + n]);
}

// ---------------- bias expand -> bf16x2 pairs along j ----------------
__global__ void __launch_bounds__(256) expand_bias_b_k(
    const float* __restrict__ table, const int* __restrict__ relidx,
    uint32_t* __restrict__ biasB)
{
    int t = blockIdx.x * 256 + threadIdx.x;      // pair index
    int i0 = relidx[2 * t], i1 = relidx[2 * t + 1];
    #pragma unroll
    for (int h = 0; h < NHEAD; h++)
        biasB[(size_t)h * (NN / 2) + t] =
            bf16pk(table[i0 * NHEAD + h], table[i1 * NHEAD + h]);
}

// ---------------- LN1: coalesced bchw read via smem transpose, bf16 out ----
__global__ void __launch_bounds__(256) ln1t_k(
    const float* __restrict__ x, const float* __restrict__ w,
    const float* __restrict__ bsh, uint32_t* __restrict__ outb)
{
    __shared__ float sm[256][33];
    __shared__ float red[8][32];
    __shared__ float musm[32], rssm[32];
    const int bb = blockIdx.y, p0 = blockIdx.x * 32;
    const int tid = threadIdx.x;

    #pragma unroll
    for (int pass = 0; pass < 8; pass++) {
        int idx = pass * 256 + tid;
        int c = idx >> 3, f = (idx & 7) * 4;
        float4 v = *(const float4*)&x[((size_t)(bb * 256 + c) << 10) + p0 + f];
        sm[c][f] = v.x; sm[c][f + 1] = v.y; sm[c][f + 2] = v.z; sm[c][f + 3] = v.w;
    }
    __syncthreads();
    const int p = tid & 31, sub = tid >> 5;
    float s = 0.0f;
    #pragma unroll
    for (int i = 0; i < 32; i++) s += sm[sub * 32 + i][p];
    red[sub][p] = s;
    __syncthreads();
    if (sub == 0) {
        float m = 0.0f;
        #pragma unroll
        for (int i = 0; i < 8; i++) m += red[i][p];
        musm[p] = m * (1.0f / 256.0f);
    }
    __syncthreads();
    float mu = musm[p], vs = 0.0f;
    #pragma unroll
    for (int i = 0; i < 32; i++) {
        float d = sm[sub * 32 + i][p] - mu;
        vs += d * d;
    }
    red[sub][p] = vs;
    __syncthreads();
    if (sub == 0) {
        float m = 0.0f;
        #pragma unroll
        for (int i = 0; i < 8; i++) m += red[i][p];
        rssm[p] = rsqrtf(m * (1.0f / 256.0f) + 1e-5f);
    }
    __syncthreads();
    const int tk = tid >> 3, ch = (tid & 7) * 32;
    const float mu2 = musm[tk], rs = rssm[tk];
    #pragma unroll
    for (int i = 0; i < 8; i++) {
        int c = ch + i * 4;
        float o0 = (sm[c][tk]     - mu2) * rs * w[c]     + bsh[c];
        float o1 = (sm[c + 1][tk] - mu2) * rs * w[c + 1] + bsh[c + 1];
        float o2 = (sm[c + 2][tk] - mu2) * rs * w[c + 2] + bsh[c + 2];
        float o3 = (sm[c + 3][tk] - mu2) * rs * w[c + 3] + bsh[c + 3];
        *(uint2*)&outb[(size_t)(bb * 1024 + p0 + tk) * 128 + c / 2] =
            make_uint2(bf16pk(o0, o1), bf16pk(o2, o3));
    }
}

// ---------------- LN2: warp per token, bf16 out ----------------
__global__ void __launch_bounds__(256) ln2w_k(
    const float* __restrict__ in, const float* __restrict__ w,
    const float* __restrict__ bsh, uint32_t* __restrict__ outb)
{
    const int token = blockIdx.x * 8 + (threadIdx.x >> 5);
    const int lane = threadIdx.x & 31;
    const float4* p = (const float4*)(in + (size_t)token * CCH);
    float4 a = p[lane], b = p[lane + 32];
    float s = a.x + a.y + a.z + a.w + b.x + b.y + b.z + b.w;
    #pragma unroll
    for (int o = 16; o; o >>= 1) s += __shfl_xor_sync(0xffffffffu, s, o);
    float mu = s * (1.0f / 256.0f);
    float v = 0.0f;
    #pragma unroll
    for (int e = 0; e < 4; e++) {
        float d0 = ((&a.x)[e] - mu), d1 = ((&b.x)[e] - mu);
        v += d0 * d0 + d1 * d1;
    }
    #pragma unroll
    for (int o = 16; o; o >>= 1) v += __shfl_xor_sync(0xffffffffu, v, o);
    float rs = rsqrtf(v * (1.0f / 256.0f) + 1e-5f);
    float4 wa = ((const float4*)w)[lane],   wb = ((const float4*)w)[lane + 32];
    float4 ba = ((const float4*)bsh)[lane], bb = ((const float4*)bsh)[lane + 32];
    float r0 = (a.x - mu) * rs * wa.x + ba.x;
    float r1 = (a.y - mu) * rs * wa.y + ba.y;
    float r2 = (a.z - mu) * rs * wa.z + ba.z;
    float r3 = (a.w - mu) * rs * wa.w + ba.w;
    float r4 = (b.x - mu) * rs * wb.x + bb.x;
    float r5 = (b.y - mu) * rs * wb.y + bb.y;
    float r6 = (b.z - mu) * rs * wb.z + bb.z;
    float r7 = (b.w - mu) * rs * wb.w + bb.w;
    uint32_t* op = outb + (size_t)token * 128;
    *(uint2*)(op + 2 * lane)      = make_uint2(bf16pk(r0, r1), bf16pk(r2, r3));
    *(uint2*)(op + 64 + 2 * lane) = make_uint2(bf16pk(r4, r5), bf16pk(r6, r7));
}

// ---------------- V transpose-pack ----------------
__global__ void __launch_bounds__(256) vt_cvt_k(
    const float* __restrict__ vf, uint32_t* __restrict__ vt)
{
    __shared__ float sm[128][33];
    const int tile = blockIdx.x, h = blockIdx.y, b = blockIdx.z;
    const int t0 = tile * 128;
    const int tid = threadIdx.x;
    #pragma unroll
    for (int pass = 0; pass < 4; pass++) {
        int idx = pass * 256 + tid;
        int tok = idx >> 3, f = (idx & 7) * 4;
        float4 v = *(const float4*)&vf[(size_t)(b * 1024 + t0 + tok) * 256
                                       + h * 32 + f];
        sm[tok][f] = v.x; sm[tok][f + 1] = v.y;
        sm[tok][f + 2] = v.z; sm[tok][f + 3] = v.w;
    }
    __syncthreads();
    const int d = tid >> 3, jb = (tid & 7) * 8;
    uint32_t wbuf[8];
    #pragma unroll
    for (int i = 0; i < 8; i++) {
        int j = jb + i;
        wbuf[i] = bf16pk(sm[2 * j][d], sm[2 * j + 1][d]);
    }
    uint32_t* dst = vt + ((size_t)(b * NHEAD + h) * 32 + d) * 512 + tile * 64 + jb;
    *(uint4*)dst       = make_uint4(wbuf[0], wbuf[1], wbuf[2], wbuf[3]);
    *(uint4*)(dst + 4) = make_uint4(wbuf[4], wbuf[5], wbuf[6], wbuf[7]);
}

// ---------------- unified bf16 GEMM m16n8k16, cp.async 2-stage ----------------
template<int EPI>
__global__ void __launch_bounds__(256, 2) gemm_b_k(
    const uint32_t* __restrict__ Ab, const uint32_t* __restrict__ Bp,
    const float* __restrict__ bias, void* __restrict__ Cv,
    int M, int N, int K,
    const float* __restrict__ aux,
    uint32_t* __restrict__ qb, uint32_t* __restrict__ kb,
    float* __restrict__ vf)
{
    __shared__ uint32_t As[2 * 128 * 20];
    __shared__ uint32_t Bs[2 * 16 * 136];

    const int tid  = threadIdx.x;
    const int w    = tid >> 5;
    const int lane = tid & 31;
    const int g    = lane >> 2;
    const int t    = lane & 3;
    const int wm   = w >> 1;
    const int wn   = w & 1;
    const int row0 = blockIdx.y * 128;
    const int col0 = blockIdx.x * 128;
    const int K2   = K / 2;

    const uint32_t asb = (uint32_t)__cvta_generic_to_shared(As);
    const uint32_t bsb = (uint32_t)__cvta_generic_to_shared(Bs);

    float acc[2][8][4] = {};

    auto loadT = [&](int k0, int s) {
        #pragma unroll
        for (int p = 0; p < 2; p++) {
            int idx = p * 256 + tid;
            int m = idx >> 2, kq = (idx & 3) * 4;
            cpa16(asb + (uint32_t)(s * 2560 + m * 20 + kq) * 4,
                  Ab + (size_t)(row0 + m) * K2 + k0 / 2 + kq);
        }
        #pragma unroll
        for (int p = 0; p < 2; p++) {
            int idx = p * 256 + tid;
            int kk = idx >> 5, nq = (idx & 31) * 4;
            cpa16(bsb + (uint32_t)(s * 2176 + kk * 136 + nq) * 4,
                  Bp + (size_t)(k0 / 2 + kk) * N + col0 + nq);
        }
    };

    const int nk = K / 32;
    loadT(0, 0); CPC();

    for (int kt = 0; kt < nk; kt++) {
        int s = kt & 1;
        if (kt + 1 < nk) loadT((kt + 1) * 32, s ^ 1);
        CPC(); CPW1();
        __syncthreads();
        const uint32_t* as = As + s * 2560;
        const uint32_t* bs = Bs + s * 2176;
        #pragma unroll
        for (int j = 0; j < 2; j++) {
            int kw = j * 8;
            uint32_t a[2][4];
            #pragma unroll
            for (int mf = 0; mf < 2; mf++) {
                int mr = wm * 32 + mf * 16 + g;
                a[mf][0] = as[mr * 20 + kw + t];
                a[mf][1] = as[(mr + 8) * 20 + kw + t];
                a[mf][2] = as[mr * 20 + kw + t + 4];
                a[mf][3] = as[(mr + 8) * 20 + kw + t + 4];
            }
            #pragma unroll
            for (int nf = 0; nf < 8; nf++) {
                int nc = wn * 64 + nf * 8 + g;
                uint32_t b0 = bs[(j * 8 + t) * 136 + nc];
                uint32_t b1 = bs[(j * 8 + t + 4) * 136 + nc];
                mma16b(acc[0][nf], a[0][0], a[0][1], a[0][2], a[0][3], b0, b1);
                mma16b(acc[1][nf], a[1][0], a[1][1], a[1][2], a[1][3], b0, b1);
            }
        }
        __syncthreads();
    }

    #pragma unroll
    for (int mf = 0; mf < 2; mf++) {
        #pragma unroll
        for (int nf = 0; nf < 8; nf++) {
            int n2 = col0 + wn * 64 + nf * 8 + 2 * t;
            #pragma unroll
            for (int half = 0; half < 2; half++) {
                int m = row0 + wm * 32 + mf * 16 + g + (half ? 8 : 0);
                float v0 = acc[mf][nf][2 * half];
                float v1 = acc[mf][nf][2 * half + 1];
                if (EPI == 0) {
                    v0 += bias[n2];
                    v1 += bias[n2 + 1];
                    v0 = 0.5f * v0 * (1.0f + erff(v0 * 0.7071067811865475f));
                    v1 = 0.5f * v1 * (1.0f + erff(v1 * 0.7071067811865475f));
                    ((uint32_t*)Cv)[(size_t)m * (N / 2) + n2 / 2] = bf16pk(v0, v1);
                } else if (EPI == 1) {
                    int bb2 = m >> 10, p = m & 1023;
                    v0 += bias[n2]     + aux[(size_t)m * CCH + n2];
                    v1 += bias[n2 + 1] + aux[(size_t)m * CCH + n2 + 1];
                    float* o = (float*)Cv;
                    o[((size_t)bb2 * CCH + n2)     * NTOK + p] = v0;
                    o[((size_t)bb2 * CCH + n2 + 1) * NTOK + p] = v1;
                } else if (EPI == 2) {
                    if (n2 < 256) {
                        qb[(size_t)m * 128 + n2 / 2] = bf16pk(v0, v1);
                    } else if (n2 < 512) {
                        kb[(size_t)m * 128 + (n2 - 256) / 2] = bf16pk(v0, v1);
                    } else {
                        vf[(size_t)m * 256 + (n2 - 512)]     = v0;
                        vf[(size_t)m * 256 + (n2 - 512) + 1] = v1;
                    }
                } else {
                    int bb2 = m >> 10, p = m & 1023;
                    v0 += bias[n2]     + aux[(((size_t)bb2 * CCH + n2) << 10) + p];
                    v1 += bias[n2 + 1] + aux[(((size_t)bb2 * CCH + n2 + 1) << 10) + p];
                    float* o = (float*)Cv;
                    o[(size_t)m * CCH + n2]     = v0;
                    o[(size_t)m * CCH + n2 + 1] = v1;
                }
            }
        }
    }
}

// ---------------- bf16 flash attention, bias in cp.async ring ----------------
// dyn smem: Ks 3*64*20, Vs 3*32*36, Bsm 3*128*36 words (84480 B total)
__global__ void __launch_bounds__(256, 2) attn_k(
    const uint32_t* __restrict__ Qb, const uint32_t* __restrict__ Kb,
    const uint32_t* __restrict__ Vt, const uint32_t* __restrict__ biasB,
    uint32_t* __restrict__ outb)
{
    extern __shared__ uint32_t dyn[];
    uint32_t* Ks  = dyn;                 // 3840 words
    uint32_t* Vs  = dyn + 3840;          // 3456 words
    uint32_t* Bsm = dyn + 7296;          // 13824 words

    const int q0 = blockIdx.x * 128;
    const int h  = blockIdx.y;
    const int b  = blockIdx.z;
    const int tid = threadIdx.x;
    const int wid = tid >> 5, lane = tid & 31;
    const int g = lane >> 2, t = lane & 3;

    const uint32_t ksb = (uint32_t)__cvta_generic_to_shared(Ks);
    const uint32_t vsb = (uint32_t)__cvta_generic_to_shared(Vs);
    const uint32_t bsb = (uint32_t)__cvta_generic_to_shared(Bsm);

    auto ldkv = [&](int kt, int s) {
        {   // K: 64 rows x 16 words
            int m = tid >> 2, kqw = (tid & 3) * 4;
            cpa16(ksb + (uint32_t)(s * 1280 + m * 20 + kqw) * 4,
                  Kb + (size_t)(b * NTOK + kt * 64 + m) * 128 + h * 16 + kqw);
        }
        {   // V: 32 d-rows x 32 words
            int m = tid >> 3, q8 = (tid & 7) * 4;
            cpa16(vsb + (uint32_t)(s * 1152 + m * 36 + q8) * 4,
                  Vt + ((size_t)(b * NHEAD + h) * 32 + m) * 512 + kt * 32 + q8);
        }
        {   // bias: 128 rows x 32 words (bf16x2)
            int r = tid >> 1, w0 = (tid & 1) * 16;
            const uint32_t* src = biasB + (size_t)h * (NN / 2)
                                  + (size_t)(q0 + r) * 512 + kt * 32 + w0;
            #pragma unroll
            for (int i = 0; i < 4; i++)
                cpa16(bsb + (uint32_t)(s * 4608 + r * 36 + w0 + i * 4) * 4,
                      src + i * 4);
        }
    };

    ldkv(0, 0); CPC();
    ldkv(1, 1); CPC();

    // Q fragments hoisted
    uint32_t qf[2][4];
    {
        const uint32_t* qp = Qb + (size_t)(b * NTOK + q0 + wid * 16) * 128 + h * 16;
        #pragma unroll
        for (int j = 0; j < 2; j++) {
            qf[j][0] = qp[(size_t)g * 128 + j * 8 + t];
            qf[j][1] = qp[(size_t)(g + 8) * 128 + j * 8 + t];
            qf[j][2] = qp[(size_t)g * 128 + j * 8 + 4 + t];
            qf[j][3] = qp[(size_t)(g + 8) * 128 + j * 8 + 4 + t];
        }
    }

    float o[4][4] = {};
    float l0 = 0.0f, l1 = 0.0f;
    const float scale = 0.17677669529663687f;

    for (int kt = 0; kt < 16; kt++) {
        int s = kt % 3;
        if (kt < 15) { CPW1(); } else { CPW0(); }
        __syncthreads();
        if (kt + 2 < 16) { ldkv(kt + 2, (kt + 2) % 3); CPC(); }
        const uint32_t* ks = Ks + s * 1280;
        const uint32_t* vs = Vs + s * 1152;
        const uint32_t* bsm = Bsm + s * 4608 + (wid * 16 + g) * 36;

        // ---- QK ----
        float c[8][4] = {};
        #pragma unroll
        for (int j = 0; j < 2; j++) {
            #pragma unroll
            for (int nf = 0; nf < 8; nf++) {
                int kc = nf * 8 + g;
                mma16b(c[nf], qf[j][0], qf[j][1], qf[j][2], qf[j][3],
                       ks[kc * 20 + j * 8 + t], ks[kc * 20 + j * 8 + 4 + t]);
            }
        }

        // ---- softmax piece (bias from smem ring) ----
        #pragma unroll
        for (int nf = 0; nf < 8; nf++) {
            float2 bA = upbf(bsm[nf * 4 + t]);
            float2 bB = upbf(bsm[288 + nf * 4 + t]);
            c[nf][0] = __expf(fmaf(c[nf][0], scale, bA.x));
            c[nf][1] = __expf(fmaf(c[nf][1], scale, bA.y));
            c[nf][2] = __expf(fmaf(c[nf][2], scale, bB.x));
            c[nf][3] = __expf(fmaf(c[nf][3], scale, bB.y));
            l0 += c[nf][0] + c[nf][1];
            l1 += c[nf][2] + c[nf][3];
        }

        // ---- PV ----
        #pragma unroll
        for (int j = 0; j < 4; j++) {
            uint32_t a0 = bf16pk(c[2 * j][0], c[2 * j][1]);
            uint32_t a1 = bf16pk(c[2 * j][2], c[2 * j][3]);
            uint32_t a2 = bf16pk(c[2 * j + 1][0], c[2 * j + 1][1]);
            uint32_t a3 = bf16pk(c[2 * j + 1][2], c[2 * j + 1][3]);
            #pragma unroll
            for (int dn = 0; dn < 4; dn++) {
                int vcb = (dn * 8 + g) * 36 + j * 8;
                mma16b(o[dn], a0, a1, a2, a3, vs[vcb + t], vs[vcb + 4 + t]);
            }
        }
    }

    l0 += __shfl_xor_sync(0xffffffffu, l0, 1);
    l0 += __shfl_xor_sync(0xffffffffu, l0, 2);
    l1 += __shfl_xor_sync(0xffffffffu, l1, 1);
    l1 += __shfl_xor_sync(0xffffffffu, l1, 2);

    float inv0 = 1.0f / l0, inv1 = 1.0f / l1;
    uint32_t* op = outb + (size_t)(b * NTOK + q0 + wid * 16 + g) * 128 + h * 16;
    #pragma unroll
    for (int dn = 0; dn < 4; dn++) {
        op[dn * 4 + t]           = bf16pk(o[dn][0] * inv0, o[dn][1] * inv0);
        op[8 * 128 + dn * 4 + t] = bf16pk(o[dn][2] * inv1, o[dn][3] * inv1);
    }
}

// ---------------- launch ----------------
extern "C" void kernel_launch(void* const* d_in, const int* in_sizes, int n_in,
                              void* d_out, int out_size)
{
    const float* x       = (const float*)d_in[0];
    const float* qkv_w   = (const float*)d_in[1];
    const float* proj_w  = (const float*)d_in[2];
    const float* proj_b  = (const float*)d_in[3];
    const float* ffn_w1  = (const float*)d_in[4];
    const float* ffn_b1  = (const float*)d_in[5];
    const float* ffn_w2  = (const float*)d_in[6];
    const float* ffn_b2  = (const float*)d_in[7];
    const float* n1w     = (const float*)d_in[8];
    const float* n1b     = (const float*)d_in[9];
    const float* n2w     = (const float*)d_in[10];
    const float* n2b     = (const float*)d_in[11];
    const float* table   = (const float*)d_in[12];
    const int*   relidx  = (const int*)d_in[13];
    float* out = (float*)d_out;

    void *px1b, *pqb, *pkb, *pvf, *pvt, *pob, *pbiasb, *px3, *px4b, *pffnb;
    void *pwqkv, *pwprj, *pw1p, *pw2p;
    cudaGetSymbolAddress(&px1b,   g_x1b);
    cudaGetSymbolAddress(&pqb,    g_qb);
    cudaGetSymbolAddress(&pkb,    g_kb);
    cudaGetSymbolAddress(&pvf,    g_vf);
    cudaGetSymbolAddress(&pvt,    g_vt);
    cudaGetSymbolAddress(&pob,    g_ob);
    cudaGetSymbolAddress(&pbiasb, g_biasb);
    cudaGetSymbolAddress(&px3,    g_x3);
    cudaGetSymbolAddress(&px4b,   g_x4b);
    cudaGetSymbolAddress(&pffnb,  g_ffnb);
    cudaGetSymbolAddress(&pwqkv,  g_wqkv);
    cudaGetSymbolAddress(&pwprj,  g_wprj);
    cudaGetSymbolAddress(&pw1p,   g_w1p);
    cudaGetSymbolAddress(&pw2p,   g_w2p);

    cudaFuncSetAttribute(attn_k, cudaFuncAttributeMaxDynamicSharedMemorySize,
                         84480);

    wcvt4_k<<<1536, 256>>>(qkv_w, proj_w, ffn_w1, ffn_w2,
                           (uint32_t*)pwqkv, (uint32_t*)pwprj,
                           (uint32_t*)pw1p, (uint32_t*)pw2p);
    expand_bias_b_k<<<NN / 512, 256>>>(table, relidx, (uint32_t*)pbiasb);

    ln1t_k<<<dim3(32, BATCH), 256>>>(x, n1w, n1b, (uint32_t*)px1b);
    gemm_b_k<2><<<dim3(6, 128), 256>>>(
        (const uint32_t*)px1b, (const uint32_t*)pwqkv, nullptr, nullptr,
        MTOT, 768, 256, nullptr,
        (uint32_t*)pqb, (uint32_t*)pkb, (float*)pvf);
    vt_cvt_k<<<dim3(8, NHEAD, BATCH), 256>>>((const float*)pvf, (uint32_t*)pvt);
    attn_k<<<dim3(NTOK / 128, NHEAD, BATCH), 256, 84480>>>(
        (const uint32_t*)pqb, (const uint32_t*)pkb, (const uint32_t*)pvt,
        (const uint32_t*)pbiasb, (uint32_t*)pob);
    gemm_b_k<3><<<dim3(2, 128), 256>>>(
        (const uint32_t*)pob, (const uint32_t*)pwprj, proj_b, px3,
        MTOT, 256, 256, x, nullptr, nullptr, nullptr);
    ln2w_k<<<MTOT / 8, 256>>>((const float*)px3, n2w, n2b, (uint32_t*)px4b);
    gemm_b_k<0><<<dim3(8, 128), 256>>>(
        (const uint32_t*)px4b, (const uint32_t*)pw1p, ffn_b1, pffnb,
        MTOT, HID, 256, nullptr, nullptr, nullptr, nullptr);
    gemm_b_k<1><<<dim3(2, 128), 256>>>(
        (const uint32_t*)pffnb, (const uint32_t*)pw2p, ffn_b2, out,
        MTOT, 256, 1024, (const float*)px3, nullptr, nullptr, nullptr);
}